// round 1
// baseline (speedup 1.0000x reference)
#include <cuda_runtime.h>
#include <math.h>

#define N_SPK 65536
#define HID   1024
#define DUP   2048
#define UMAT  3072
#define LN_EPS 1e-5f
#define LOGITS_BLOCKS 8192   // 8 rows per block

// ---- scratch (allocation-free: __device__ globals) ----
__device__ float g_query[HID];
__device__ float g_logits[N_SPK];
__device__ float g_blockmax[LOGITS_BLOCKS];
__device__ float g_max;
__device__ float g_sum;
__device__ float g_context[HID];
__device__ float g_hmid[DUP];
__device__ float g_ovec[HID];

__device__ __forceinline__ float warp_sum(float v) {
#pragma unroll
    for (int o = 16; o > 0; o >>= 1) v += __shfl_xor_sync(0xffffffffu, v, o);
    return v;
}
__device__ __forceinline__ float warp_max(float v) {
#pragma unroll
    for (int o = 16; o > 0; o >>= 1) v = fmaxf(v, __shfl_xor_sync(0xffffffffu, v, o));
    return v;
}

// K0: zero the accumulators (must run every graph replay)
__global__ void k_init() {
    int t = blockIdx.x * blockDim.x + threadIdx.x;
    if (t < HID) g_context[t] = 0.f;
    if (t == 0) g_sum = 0.f;
}

// K1: query = W_attn @ u_t  (one warp per output row)
__global__ void k_query(const float* __restrict__ W_attn, const float* __restrict__ u_t) {
    __shared__ float u[HID];
    for (int i = threadIdx.x; i < HID; i += blockDim.x) u[i] = u_t[i];
    __syncthreads();
    int warp = threadIdx.x >> 5, lane = threadIdx.x & 31;
    int row = blockIdx.x * (blockDim.x >> 5) + warp;
    const float4* w  = (const float4*)(W_attn + (size_t)row * HID);
    const float4* u4 = (const float4*)u;
    float s = 0.f;
#pragma unroll
    for (int k = 0; k < 8; k++) {
        int idx = lane + 32 * k;
        float4 a = w[idx], b = u4[idx];
        s += a.x * b.x + a.y * b.y + a.z * b.z + a.w * b.w;
    }
    s = warp_sum(s);
    if (lane == 0) g_query[row] = s;
}

// K2: logits[i] = dot(SE[i], query); per-block max into g_blockmax
__global__ void k_logits(const float* __restrict__ SE) {
    __shared__ float q[HID];
    __shared__ float wmax[8];
    for (int i = threadIdx.x; i < HID; i += blockDim.x) q[i] = g_query[i];
    __syncthreads();
    int warp = threadIdx.x >> 5, lane = threadIdx.x & 31;
    int row = blockIdx.x * 8 + warp;
    const float4* r  = (const float4*)(SE + (size_t)row * HID);
    const float4* q4 = (const float4*)q;
    float s = 0.f;
#pragma unroll
    for (int k = 0; k < 8; k++) {
        int idx = lane + 32 * k;
        float4 a = r[idx], b = q4[idx];
        s += a.x * b.x + a.y * b.y + a.z * b.z + a.w * b.w;
    }
    s = warp_sum(s);
    if (lane == 0) { g_logits[row] = s; wmax[warp] = s; }
    __syncthreads();
    if (threadIdx.x == 0) {
        float m = wmax[0];
#pragma unroll
        for (int i = 1; i < 8; i++) m = fmaxf(m, wmax[i]);
        g_blockmax[blockIdx.x] = m;
    }
}

// K3: global max over block maxima (single block, 1024 threads)
__global__ void k_max() {
    __shared__ float sm[32];
    int t = threadIdx.x;
    float m = -INFINITY;
#pragma unroll
    for (int k = 0; k < LOGITS_BLOCKS / 1024; k++)
        m = fmaxf(m, g_blockmax[t + 1024 * k]);
    m = warp_max(m);
    if ((t & 31) == 0) sm[t >> 5] = m;
    __syncthreads();
    if (t < 32) {
        m = warp_max(sm[t]);
        if (t == 0) g_max = m;
    }
}

// K4: g_sum = sum(exp(logit - max))
__global__ void k_sumexp() {
    __shared__ float sm[32];
    int i = blockIdx.x * 1024 + threadIdx.x;
    float gm = g_max;
    float v = expf(g_logits[i] - gm);
    v = warp_sum(v);
    if ((threadIdx.x & 31) == 0) sm[threadIdx.x >> 5] = v;
    __syncthreads();
    if (threadIdx.x < 32) {
        v = warp_sum(sm[threadIdx.x]);
        if (threadIdx.x == 0) atomicAdd(&g_sum, v);
    }
}

// K5: FUSED full-array copy + context accumulation.
// 2048 blocks x 32 rows. Thread t always owns columns [4t, 4t+4) -> register
// float4 accumulator, 4 atomicAdds per thread at the end.
__global__ void k_ctx_copy(const float* __restrict__ SE, float* __restrict__ out) {
    __shared__ float w[32];
    int base = blockIdx.x * 32;
    if (threadIdx.x < 32) {
        float invZ = 1.f / g_sum;
        w[threadIdx.x] = expf(g_logits[base + threadIdx.x] - g_max) * invZ;
    }
    __syncthreads();
    int t = threadIdx.x;
    const float4* se4  = (const float4*)SE;
    float4*       out4 = (float4*)out;
    float4 acc = make_float4(0.f, 0.f, 0.f, 0.f);
#pragma unroll 4
    for (int r = 0; r < 32; r++) {
        size_t idx = (size_t)(base + r) * (HID / 4) + t;
        float4 v = se4[idx];
        out4[idx] = v;
        float wr = w[r];
        acc.x = fmaf(wr, v.x, acc.x);
        acc.y = fmaf(wr, v.y, acc.y);
        acc.z = fmaf(wr, v.z, acc.z);
        acc.w = fmaf(wr, v.w, acc.w);
    }
    float* ctx = g_context + t * 4;
    atomicAdd(ctx + 0, acc.x);
    atomicAdd(ctx + 1, acc.y);
    atomicAdd(ctx + 2, acc.z);
    atomicAdd(ctx + 3, acc.w);
}

// K6: h = gelu(W1 @ concat(u_t, h_s, context) + b1)  (one warp per output)
__global__ void k_h(const float* __restrict__ W1, const float* __restrict__ b1,
                    const float* __restrict__ u_t, const float* __restrict__ SE,
                    const int* __restrict__ s_i_p) {
    __shared__ float um[UMAT];
    int si = *s_i_p;
    for (int i = threadIdx.x; i < UMAT; i += blockDim.x) {
        float v;
        if (i < 1024)      v = u_t[i];
        else if (i < 2048) v = SE[(size_t)si * HID + (i - 1024)];
        else               v = g_context[i - 2048];
        um[i] = v;
    }
    __syncthreads();
    int warp = threadIdx.x >> 5, lane = threadIdx.x & 31;
    int row = blockIdx.x * 8 + warp;
    const float4* wrow = (const float4*)(W1 + (size_t)row * UMAT);
    const float4* u4   = (const float4*)um;
    float s = 0.f;
#pragma unroll
    for (int k = 0; k < 24; k++) {
        int idx = lane + 32 * k;
        float4 a = wrow[idx], b = u4[idx];
        s += a.x * b.x + a.y * b.y + a.z * b.z + a.w * b.w;
    }
    s = warp_sum(s);
    if (lane == 0) {
        float x = s + b1[row];
        g_hmid[row] = 0.5f * x * (1.f + erff(x * 0.70710678118654752f));
    }
}

// K7: o = W2 @ h + b2
__global__ void k_o(const float* __restrict__ W2, const float* __restrict__ b2) {
    __shared__ float h[DUP];
    for (int i = threadIdx.x; i < DUP; i += blockDim.x) h[i] = g_hmid[i];
    __syncthreads();
    int warp = threadIdx.x >> 5, lane = threadIdx.x & 31;
    int row = blockIdx.x * 8 + warp;
    const float4* wrow = (const float4*)(W2 + (size_t)row * DUP);
    const float4* h4   = (const float4*)h;
    float s = 0.f;
#pragma unroll
    for (int k = 0; k < 16; k++) {
        int idx = lane + 32 * k;
        float4 a = wrow[idx], b = h4[idx];
        s += a.x * b.x + a.y * b.y + a.z * b.z + a.w * b.w;
    }
    s = warp_sum(s);
    if (lane == 0) g_ovec[row] = s + b2[row];
}

// K8: LayerNorm over o + residual scatter of row s_i (single block, 1024 threads)
__global__ void k_ln_scatter(const float* __restrict__ SE,
                             const float* __restrict__ gamma,
                             const float* __restrict__ beta,
                             const int* __restrict__ s_i_p,
                             float* __restrict__ out) {
    __shared__ float sm[32];
    __shared__ float s_mu, s_rstd;
    int t = threadIdx.x;
    float o = g_ovec[t];

    float v = warp_sum(o);
    if ((t & 31) == 0) sm[t >> 5] = v;
    __syncthreads();
    if (t < 32) {
        v = warp_sum(sm[t]);
        if (t == 0) s_mu = v * (1.f / 1024.f);
    }
    __syncthreads();

    float d = o - s_mu;
    v = warp_sum(d * d);
    __syncthreads();           // protect sm reuse
    if ((t & 31) == 0) sm[t >> 5] = v;
    __syncthreads();
    if (t < 32) {
        v = warp_sum(sm[t]);
        if (t == 0) s_rstd = rsqrtf(v * (1.f / 1024.f) + LN_EPS);
    }
    __syncthreads();

    int si = *s_i_p;
    float hs = SE[(size_t)si * HID + t];
    out[(size_t)si * HID + t] = hs + d * s_rstd * gamma[t] + beta[t];
}

extern "C" void kernel_launch(void* const* d_in, const int* in_sizes, int n_in,
                              void* d_out, int out_size) {
    const float* u_t    = (const float*)d_in[0];
    const float* SE     = (const float*)d_in[1];
    const float* W_attn = (const float*)d_in[2];
    const float* W1     = (const float*)d_in[3];
    const float* b1     = (const float*)d_in[4];
    const float* W2     = (const float*)d_in[5];
    const float* b2     = (const float*)d_in[6];
    const float* gamma  = (const float*)d_in[7];
    const float* beta   = (const float*)d_in[8];
    const int*   s_i    = (const int*)d_in[9];
    float* out = (float*)d_out;

    k_init<<<4, 256>>>();
    k_query<<<128, 256>>>(W_attn, u_t);
    k_logits<<<LOGITS_BLOCKS, 256>>>(SE);
    k_max<<<1, 1024>>>();
    k_sumexp<<<64, 1024>>>();
    k_ctx_copy<<<2048, 256>>>(SE, out);
    k_h<<<256, 256>>>(W1, b1, u_t, SE, s_i);
    k_o<<<128, 256>>>(W2, b2);
    k_ln_scatter<<<1, 1024>>>(SE, gamma, beta, s_i, out);
}

// round 2
// speedup vs baseline: 1.5667x; 1.5667x over previous
#include <cuda_runtime.h>
#include <math.h>

#define N_SPK 65536
#define HID   1024
#define DUP   2048
#define UMAT  3072
#define LN_EPS 1e-5f

#define ROWS_PER_WARP 32
#define WARPS_TOTAL   (N_SPK / ROWS_PER_WARP)   // 2048
#define FUSED_BLOCKS  (WARPS_TOTAL / 8)          // 256 blocks x 8 warps

// ---- scratch (allocation-free: __device__ globals) ----
__device__ float g_query[HID];
__device__ float g_wm[WARPS_TOTAL];              // per-warp running max
__device__ float g_ws[WARPS_TOTAL];              // per-warp running sum
__device__ float g_wv[WARPS_TOTAL * HID];        // per-warp weighted vectors (8 MB)
__device__ float g_context[HID];
__device__ float g_hmid[DUP];
__device__ float g_ovec[HID];

__device__ __forceinline__ float warp_sum(float v) {
#pragma unroll
    for (int o = 16; o > 0; o >>= 1) v += __shfl_xor_sync(0xffffffffu, v, o);
    return v;
}
__device__ __forceinline__ float warp_max(float v) {
#pragma unroll
    for (int o = 16; o > 0; o >>= 1) v = fmaxf(v, __shfl_xor_sync(0xffffffffu, v, o));
    return v;
}

// K1: query = W_attn @ u_t  (one warp per output row) + zero g_context
__global__ void k_query(const float* __restrict__ W_attn, const float* __restrict__ u_t) {
    int gtid = blockIdx.x * blockDim.x + threadIdx.x;
    if (gtid < HID) g_context[gtid] = 0.f;

    __shared__ float u[HID];
    for (int i = threadIdx.x; i < HID; i += blockDim.x) u[i] = u_t[i];
    __syncthreads();
    int warp = threadIdx.x >> 5, lane = threadIdx.x & 31;
    int row = blockIdx.x * (blockDim.x >> 5) + warp;
    const float4* w  = (const float4*)(W_attn + (size_t)row * HID);
    const float4* u4 = (const float4*)u;
    float s = 0.f;
#pragma unroll
    for (int k = 0; k < 8; k++) {
        int idx = lane + 32 * k;
        float4 a = w[idx], b = u4[idx];
        s += a.x * b.x + a.y * b.y + a.z * b.z + a.w * b.w;
    }
    s = warp_sum(s);
    if (lane == 0) g_query[row] = s;
}

// K2: FUSED single pass over the bank.
// Per warp: 32 consecutive rows. For each row:
//   - load row (8 x float4/lane), stream-copy it to out,
//   - logit = dot(row, query) via warp shuffle reduction,
//   - online-softmax rescale + weighted accumulate into register acc.
// Outputs per warp: (m, s, 1024-float weighted partial vector).
__global__ void __launch_bounds__(256, 2)
k_fused(const float* __restrict__ SE, float* __restrict__ out) {
    __shared__ float q[HID];
    for (int i = threadIdx.x; i < HID; i += blockDim.x) q[i] = g_query[i];
    __syncthreads();

    int warp = threadIdx.x >> 5, lane = threadIdx.x & 31;
    int w = blockIdx.x * 8 + warp;
    size_t base = (size_t)w * ROWS_PER_WARP * (HID / 4);   // float4 units

    const float4* se4  = (const float4*)SE;
    float4*       out4 = (float4*)out;
    const float4* q4   = (const float4*)q;

    float4 v0[8], v1[8], acc[8];
#pragma unroll
    for (int k = 0; k < 8; k++) acc[k] = make_float4(0.f, 0.f, 0.f, 0.f);
    float m = -INFINITY, s = 0.f;

#pragma unroll
    for (int k = 0; k < 8; k++) v0[k] = se4[base + k * 32 + lane];

    for (int r = 0; r < ROWS_PER_WARP; r++) {
        size_t rb = base + (size_t)r * (HID / 4);
        if (r + 1 < ROWS_PER_WARP) {
#pragma unroll
            for (int k = 0; k < 8; k++) v1[k] = se4[rb + (HID / 4) + k * 32 + lane];
        }
        // logit
        float p = 0.f;
#pragma unroll
        for (int k = 0; k < 8; k++) {
            float4 qq = q4[k * 32 + lane];
            p += v0[k].x * qq.x + v0[k].y * qq.y + v0[k].z * qq.z + v0[k].w * qq.w;
        }
        p = warp_sum(p);

        float mn = fmaxf(m, p);
        float sc = expf(m - mn);        // first iter: exp(-inf)=0
        float wt = expf(p - mn);
        s = s * sc + wt;
        m = mn;
#pragma unroll
        for (int k = 0; k < 8; k++) {
            out4[rb + k * 32 + lane] = v0[k];
            acc[k].x = fmaf(acc[k].x, sc, wt * v0[k].x);
            acc[k].y = fmaf(acc[k].y, sc, wt * v0[k].y);
            acc[k].z = fmaf(acc[k].z, sc, wt * v0[k].z);
            acc[k].w = fmaf(acc[k].w, sc, wt * v0[k].w);
        }
#pragma unroll
        for (int k = 0; k < 8; k++) v0[k] = v1[k];
    }

    if (lane == 0) { g_wm[w] = m; g_ws[w] = s; }
    float4* vp = (float4*)g_wv + (size_t)w * (HID / 4);
#pragma unroll
    for (int k = 0; k < 8; k++) vp[k * 32 + lane] = acc[k];
}

// K3: combine per-warp partials -> g_context.
// 64 blocks x 256 threads. Each block redundantly computes global M and S
// (cheap: 2048 floats), then reduces 32 warp-partials into register float4
// and atomically adds to g_context (64 atomics per address).
__global__ void k_ctx() {
    __shared__ float sm[32];
    __shared__ float sM, sS;
    __shared__ float e[32];
    int t = threadIdx.x;
    int lane = t & 31, wid = t >> 5;

    // global max over 2048 warp maxima
    float mv[8];
#pragma unroll
    for (int j = 0; j < 8; j++) mv[j] = g_wm[t + 256 * j];
    float m = mv[0];
#pragma unroll
    for (int j = 1; j < 8; j++) m = fmaxf(m, mv[j]);
    m = warp_max(m);
    if (lane == 0) sm[wid] = m;
    __syncthreads();
    if (t < 32) {
        float x = (t < 8) ? sm[t] : -INFINITY;
        x = warp_max(x);
        if (t == 0) sM = x;
    }
    __syncthreads();
    float M = sM;

    // global sum
    float ss = 0.f;
#pragma unroll
    for (int j = 0; j < 8; j++) ss += g_ws[t + 256 * j] * expf(mv[j] - M);
    ss = warp_sum(ss);
    __syncthreads();
    if (lane == 0) sm[wid] = ss;
    __syncthreads();
    if (t < 32) {
        float x = (t < 8) ? sm[t] : 0.f;
        x = warp_sum(x);
        if (t == 0) sS = x;
    }
    __syncthreads();
    float invS = 1.f / sS;

    int wbase = blockIdx.x * 32;
    if (t < 32) e[t] = expf(g_wm[wbase + t] - M) * invS;
    __syncthreads();

    const float4* v4 = (const float4*)g_wv;
    float4 acc = make_float4(0.f, 0.f, 0.f, 0.f);
#pragma unroll 4
    for (int j = 0; j < 32; j++) {
        float4 v = v4[(size_t)(wbase + j) * (HID / 4) + t];
        float ee = e[j];
        acc.x = fmaf(ee, v.x, acc.x);
        acc.y = fmaf(ee, v.y, acc.y);
        acc.z = fmaf(ee, v.z, acc.z);
        acc.w = fmaf(ee, v.w, acc.w);
    }
    float* ctx = g_context + t * 4;
    atomicAdd(ctx + 0, acc.x);
    atomicAdd(ctx + 1, acc.y);
    atomicAdd(ctx + 2, acc.z);
    atomicAdd(ctx + 3, acc.w);
}

// K4: h = gelu(W1 @ concat(u_t, h_s, context) + b1)  (one warp per output)
__global__ void k_h(const float* __restrict__ W1, const float* __restrict__ b1,
                    const float* __restrict__ u_t, const float* __restrict__ SE,
                    const int* __restrict__ s_i_p) {
    __shared__ float um[UMAT];
    int si = *s_i_p;
    for (int i = threadIdx.x; i < UMAT; i += blockDim.x) {
        float v;
        if (i < 1024)      v = u_t[i];
        else if (i < 2048) v = SE[(size_t)si * HID + (i - 1024)];
        else               v = g_context[i - 2048];
        um[i] = v;
    }
    __syncthreads();
    int warp = threadIdx.x >> 5, lane = threadIdx.x & 31;
    int row = blockIdx.x * 8 + warp;
    const float4* wrow = (const float4*)(W1 + (size_t)row * UMAT);
    const float4* u4   = (const float4*)um;
    float s = 0.f;
#pragma unroll
    for (int k = 0; k < 24; k++) {
        int idx = lane + 32 * k;
        float4 a = wrow[idx], b = u4[idx];
        s += a.x * b.x + a.y * b.y + a.z * b.z + a.w * b.w;
    }
    s = warp_sum(s);
    if (lane == 0) {
        float x = s + b1[row];
        g_hmid[row] = 0.5f * x * (1.f + erff(x * 0.70710678118654752f));
    }
}

// K5: o = W2 @ h + b2
__global__ void k_o(const float* __restrict__ W2, const float* __restrict__ b2) {
    __shared__ float h[DUP];
    for (int i = threadIdx.x; i < DUP; i += blockDim.x) h[i] = g_hmid[i];
    __syncthreads();
    int warp = threadIdx.x >> 5, lane = threadIdx.x & 31;
    int row = blockIdx.x * 8 + warp;
    const float4* wrow = (const float4*)(W2 + (size_t)row * DUP);
    const float4* h4   = (const float4*)h;
    float s = 0.f;
#pragma unroll
    for (int k = 0; k < 16; k++) {
        int idx = lane + 32 * k;
        float4 a = wrow[idx], b = h4[idx];
        s += a.x * b.x + a.y * b.y + a.z * b.z + a.w * b.w;
    }
    s = warp_sum(s);
    if (lane == 0) g_ovec[row] = s + b2[row];
}

// K6: LayerNorm over o + residual scatter of row s_i (single block, 1024 threads)
__global__ void k_ln_scatter(const float* __restrict__ SE,
                             const float* __restrict__ gamma,
                             const float* __restrict__ beta,
                             const int* __restrict__ s_i_p,
                             float* __restrict__ out) {
    __shared__ float sm[32];
    __shared__ float s_mu, s_rstd;
    int t = threadIdx.x;
    float o = g_ovec[t];

    float v = warp_sum(o);
    if ((t & 31) == 0) sm[t >> 5] = v;
    __syncthreads();
    if (t < 32) {
        v = warp_sum(sm[t]);
        if (t == 0) s_mu = v * (1.f / 1024.f);
    }
    __syncthreads();

    float d = o - s_mu;
    v = warp_sum(d * d);
    __syncthreads();
    if ((t & 31) == 0) sm[t >> 5] = v;
    __syncthreads();
    if (t < 32) {
        v = warp_sum(sm[t]);
        if (t == 0) s_rstd = rsqrtf(v * (1.f / 1024.f) + LN_EPS);
    }
    __syncthreads();

    int si = *s_i_p;
    float hs = SE[(size_t)si * HID + t];
    out[(size_t)si * HID + t] = hs + d * s_rstd * gamma[t] + beta[t];
}

extern "C" void kernel_launch(void* const* d_in, const int* in_sizes, int n_in,
                              void* d_out, int out_size) {
    const float* u_t    = (const float*)d_in[0];
    const float* SE     = (const float*)d_in[1];
    const float* W_attn = (const float*)d_in[2];
    const float* W1     = (const float*)d_in[3];
    const float* b1     = (const float*)d_in[4];
    const float* W2     = (const float*)d_in[5];
    const float* b2     = (const float*)d_in[6];
    const float* gamma  = (const float*)d_in[7];
    const float* beta   = (const float*)d_in[8];
    const int*   s_i    = (const int*)d_in[9];
    float* out = (float*)d_out;

    k_query<<<128, 256>>>(W_attn, u_t);
    k_fused<<<FUSED_BLOCKS, 256>>>(SE, out);
    k_ctx<<<64, 256>>>();
    k_h<<<256, 256>>>(W1, b1, u_t, SE, s_i);
    k_o<<<128, 256>>>(W2, b2);
    k_ln_scatter<<<1, 1024>>>(SE, gamma, beta, s_i, out);
}

// round 3
// speedup vs baseline: 1.6936x; 1.0810x over previous
#include <cuda_runtime.h>
#include <math.h>

#define N_SPK 65536
#define HID   1024
#define DUP   2048
#define UMAT  3072
#define LN_EPS 1e-5f

#define ROWS_PER_WARP 16
#define WARPS_TOTAL   (N_SPK / ROWS_PER_WARP)    // 4096
#define FUSED_BLOCKS  (WARPS_TOTAL / 8)           // 512 blocks x 8 warps

// ---- scratch (allocation-free: __device__ globals) ----
__device__ float g_query[HID];
__device__ float g_wm[WARPS_TOTAL];               // per-warp running max
__device__ float g_ws[WARPS_TOTAL];               // per-warp running sum
__device__ float g_wv[WARPS_TOTAL * HID];         // per-warp weighted vectors (16 MB)
__device__ float g_context[HID];
__device__ float g_hmid[DUP];
__device__ float g_ovec[HID];

__device__ __forceinline__ float warp_sum(float v) {
#pragma unroll
    for (int o = 16; o > 0; o >>= 1) v += __shfl_xor_sync(0xffffffffu, v, o);
    return v;
}
__device__ __forceinline__ float warp_max(float v) {
#pragma unroll
    for (int o = 16; o > 0; o >>= 1) v = fmaxf(v, __shfl_xor_sync(0xffffffffu, v, o));
    return v;
}

// Block-wide sum over 256 threads; result valid on thread 0.
__device__ __forceinline__ float block_sum256(float v, float* sm) {
    int lane = threadIdx.x & 31, wid = threadIdx.x >> 5;
    v = warp_sum(v);
    if (lane == 0) sm[wid] = v;
    __syncthreads();
    float r = 0.f;
    if (wid == 0) {
        float x = (lane < 8) ? sm[lane] : 0.f;
        r = warp_sum(x);
    }
    return r;
}

// K1: query[row] = dot(W_attn[row], u_t). One block (256 thr) per row.
// Blocks 0..3 also zero g_context.
__global__ void k_query(const float* __restrict__ W_attn, const float* __restrict__ u_t) {
    __shared__ float sm[8];
    if (blockIdx.x < 4) g_context[blockIdx.x * 256 + threadIdx.x] = 0.f;

    int row = blockIdx.x;
    const float4* w  = (const float4*)(W_attn + (size_t)row * HID);
    const float4* u4 = (const float4*)u_t;
    int t = threadIdx.x;
    float4 a = w[t], b = u4[t];
    float s = a.x * b.x + a.y * b.y + a.z * b.z + a.w * b.w;
    s = block_sum256(s, sm);
    if (t == 0) g_query[row] = s;
}

// K2: FUSED single pass over the bank: copy + logits + online-softmax context.
__global__ void __launch_bounds__(256, 2)
k_fused(const float* __restrict__ SE, float* __restrict__ out) {
    __shared__ float q[HID];
    for (int i = threadIdx.x; i < HID; i += blockDim.x) q[i] = g_query[i];
    __syncthreads();

    int warp = threadIdx.x >> 5, lane = threadIdx.x & 31;
    int w = blockIdx.x * 8 + warp;
    size_t base = (size_t)w * ROWS_PER_WARP * (HID / 4);   // float4 units

    const float4* se4  = (const float4*)SE;
    float4*       out4 = (float4*)out;
    const float4* q4   = (const float4*)q;

    float4 v0[8], v1[8], acc[8];
#pragma unroll
    for (int k = 0; k < 8; k++) acc[k] = make_float4(0.f, 0.f, 0.f, 0.f);
    float m = -INFINITY, s = 0.f;

#pragma unroll
    for (int k = 0; k < 8; k++) v0[k] = __ldcs(&se4[base + k * 32 + lane]);

    for (int r = 0; r < ROWS_PER_WARP; r++) {
        size_t rb = base + (size_t)r * (HID / 4);
        if (r + 1 < ROWS_PER_WARP) {
#pragma unroll
            for (int k = 0; k < 8; k++) v1[k] = __ldcs(&se4[rb + (HID / 4) + k * 32 + lane]);
        }
        float p = 0.f;
#pragma unroll
        for (int k = 0; k < 8; k++) {
            float4 qq = q4[k * 32 + lane];
            p += v0[k].x * qq.x + v0[k].y * qq.y + v0[k].z * qq.z + v0[k].w * qq.w;
        }
        p = warp_sum(p);

        float mn = fmaxf(m, p);
        float sc = expf(m - mn);        // first iter: exp(-inf)=0
        float wt = expf(p - mn);
        s = s * sc + wt;
        m = mn;
#pragma unroll
        for (int k = 0; k < 8; k++) {
            __stcs(&out4[rb + k * 32 + lane], v0[k]);
            acc[k].x = fmaf(acc[k].x, sc, wt * v0[k].x);
            acc[k].y = fmaf(acc[k].y, sc, wt * v0[k].y);
            acc[k].z = fmaf(acc[k].z, sc, wt * v0[k].z);
            acc[k].w = fmaf(acc[k].w, sc, wt * v0[k].w);
        }
#pragma unroll
        for (int k = 0; k < 8; k++) v0[k] = v1[k];
    }

    if (lane == 0) { g_wm[w] = m; g_ws[w] = s; }
    float4* vp = (float4*)g_wv + (size_t)w * (HID / 4);
#pragma unroll
    for (int k = 0; k < 8; k++) vp[k * 32 + lane] = acc[k];
}

// K3: combine 4096 per-warp partials -> g_context.
// 128 blocks; each block redundantly computes global M,S (4096 floats), then
// reduces 32 partial vectors and atomically adds (128 atomics per address).
__global__ void k_ctx() {
    __shared__ float sm[32];
    __shared__ float sM, sS;
    __shared__ float e[32];
    int t = threadIdx.x;
    int lane = t & 31, wid = t >> 5;

    // global max over 4096 warp maxima
    float mv[16];
#pragma unroll
    for (int j = 0; j < 16; j++) mv[j] = g_wm[t + 256 * j];
    float m = mv[0];
#pragma unroll
    for (int j = 1; j < 16; j++) m = fmaxf(m, mv[j]);
    m = warp_max(m);
    if (lane == 0) sm[wid] = m;
    __syncthreads();
    if (t < 32) {
        float x = (t < 8) ? sm[t] : -INFINITY;
        x = warp_max(x);
        if (t == 0) sM = x;
    }
    __syncthreads();
    float M = sM;

    // global sum
    float ss = 0.f;
#pragma unroll
    for (int j = 0; j < 16; j++) ss += g_ws[t + 256 * j] * expf(mv[j] - M);
    ss = warp_sum(ss);
    __syncthreads();
    if (lane == 0) sm[wid] = ss;
    __syncthreads();
    if (t < 32) {
        float x = (t < 8) ? sm[t] : 0.f;
        x = warp_sum(x);
        if (t == 0) sS = x;
    }
    __syncthreads();
    float invS = 1.f / sS;

    int wbase = blockIdx.x * 32;
    if (t < 32) e[t] = expf(g_wm[wbase + t] - M) * invS;
    __syncthreads();

    const float4* v4 = (const float4*)g_wv;
    float4 acc = make_float4(0.f, 0.f, 0.f, 0.f);
#pragma unroll 4
    for (int j = 0; j < 32; j++) {
        float4 v = __ldcs(&v4[(size_t)(wbase + j) * (HID / 4) + t]);
        float ee = e[j];
        acc.x = fmaf(ee, v.x, acc.x);
        acc.y = fmaf(ee, v.y, acc.y);
        acc.z = fmaf(ee, v.z, acc.z);
        acc.w = fmaf(ee, v.w, acc.w);
    }
    float* ctx = g_context + t * 4;
    atomicAdd(ctx + 0, acc.x);
    atomicAdd(ctx + 1, acc.y);
    atomicAdd(ctx + 2, acc.z);
    atomicAdd(ctx + 3, acc.w);
}

// K4: h[row] = gelu(dot(W1[row], um) + b1[row]). One block (256 thr) per row.
__global__ void k_h(const float* __restrict__ W1, const float* __restrict__ b1,
                    const float* __restrict__ u_t, const float* __restrict__ SE,
                    const int* __restrict__ s_i_p) {
    __shared__ float um[UMAT];
    __shared__ float sm[8];
    int si = *s_i_p;
    for (int i = threadIdx.x; i < UMAT; i += blockDim.x) {
        float v;
        if (i < 1024)      v = u_t[i];
        else if (i < 2048) v = SE[(size_t)si * HID + (i - 1024)];
        else               v = g_context[i - 2048];
        um[i] = v;
    }
    __syncthreads();
    int row = blockIdx.x, t = threadIdx.x;
    const float4* wrow = (const float4*)(W1 + (size_t)row * UMAT);
    const float4* u4   = (const float4*)um;
    float s = 0.f;
#pragma unroll
    for (int k = 0; k < 3; k++) {
        int idx = t + 256 * k;
        float4 a = __ldcs(&wrow[idx]);
        float4 b = u4[idx];
        s += a.x * b.x + a.y * b.y + a.z * b.z + a.w * b.w;
    }
    s = block_sum256(s, sm);
    if (t == 0) {
        float x = s + b1[row];
        g_hmid[row] = 0.5f * x * (1.f + erff(x * 0.70710678118654752f));
    }
}

// K5: o[row] = dot(W2[row], h) + b2[row]. One block (256 thr) per row.
__global__ void k_o(const float* __restrict__ W2, const float* __restrict__ b2) {
    __shared__ float h[DUP];
    __shared__ float sm[8];
    for (int i = threadIdx.x; i < DUP; i += blockDim.x) h[i] = g_hmid[i];
    __syncthreads();
    int row = blockIdx.x, t = threadIdx.x;
    const float4* wrow = (const float4*)(W2 + (size_t)row * DUP);
    const float4* h4   = (const float4*)h;
    float s = 0.f;
#pragma unroll
    for (int k = 0; k < 2; k++) {
        int idx = t + 256 * k;
        float4 a = __ldcs(&wrow[idx]);
        float4 b = h4[idx];
        s += a.x * b.x + a.y * b.y + a.z * b.z + a.w * b.w;
    }
    s = block_sum256(s, sm);
    if (t == 0) g_ovec[row] = s + b2[row];
}

// K6: LayerNorm over o + residual scatter of row s_i (single block, 1024 threads)
__global__ void k_ln_scatter(const float* __restrict__ SE,
                             const float* __restrict__ gamma,
                             const float* __restrict__ beta,
                             const int* __restrict__ s_i_p,
                             float* __restrict__ out) {
    __shared__ float sm[32];
    __shared__ float s_mu, s_rstd;
    int t = threadIdx.x;
    float o = g_ovec[t];

    float v = warp_sum(o);
    if ((t & 31) == 0) sm[t >> 5] = v;
    __syncthreads();
    if (t < 32) {
        v = warp_sum(sm[t]);
        if (t == 0) s_mu = v * (1.f / 1024.f);
    }
    __syncthreads();

    float d = o - s_mu;
    v = warp_sum(d * d);
    __syncthreads();
    if ((t & 31) == 0) sm[t >> 5] = v;
    __syncthreads();
    if (t < 32) {
        v = warp_sum(sm[t]);
        if (t == 0) s_rstd = rsqrtf(v * (1.f / 1024.f) + LN_EPS);
    }
    __syncthreads();

    int si = *s_i_p;
    float hs = SE[(size_t)si * HID + t];
    out[(size_t)si * HID + t] = hs + d * s_rstd * gamma[t] + beta[t];
}

extern "C" void kernel_launch(void* const* d_in, const int* in_sizes, int n_in,
                              void* d_out, int out_size) {
    const float* u_t    = (const float*)d_in[0];
    const float* SE     = (const float*)d_in[1];
    const float* W_attn = (const float*)d_in[2];
    const float* W1     = (const float*)d_in[3];
    const float* b1     = (const float*)d_in[4];
    const float* W2     = (const float*)d_in[5];
    const float* b2     = (const float*)d_in[6];
    const float* gamma  = (const float*)d_in[7];
    const float* beta   = (const float*)d_in[8];
    const int*   s_i    = (const int*)d_in[9];
    float* out = (float*)d_out;

    k_query<<<HID, 256>>>(W_attn, u_t);
    k_fused<<<FUSED_BLOCKS, 256>>>(SE, out);
    k_ctx<<<128, 256>>>();
    k_h<<<DUP, 256>>>(W1, b1, u_t, SE, s_i);
    k_o<<<HID, 256>>>(W2, b2);
    k_ln_scatter<<<1, 1024>>>(SE, gamma, beta, s_i, out);
}

// round 4
// speedup vs baseline: 1.7221x; 1.0168x over previous
#include <cuda_runtime.h>
#include <math.h>

#define N_SPK 65536
#define HID   1024
#define DUP   2048
#define UMAT  3072
#define LN_EPS 1e-5f

#define ROWS_PER_WARP 32
#define WARPS_TOTAL   (N_SPK / ROWS_PER_WARP)    // 2048
#define FUSED_BLOCKS  (WARPS_TOTAL / 8)           // 256 blocks x 8 warps

// ---- scratch (allocation-free: __device__ globals) ----
__device__ float g_query[HID];
__device__ float g_wm[WARPS_TOTAL];               // per-warp running max
__device__ float g_ws[WARPS_TOTAL];               // per-warp running sum
__device__ float g_wv[WARPS_TOTAL * HID];         // per-warp weighted vectors (8 MB)
__device__ float g_context[HID];
__device__ float g_hmid[DUP];
__device__ float g_ovec[HID];

__device__ __forceinline__ float warp_sum(float v) {
#pragma unroll
    for (int o = 16; o > 0; o >>= 1) v += __shfl_xor_sync(0xffffffffu, v, o);
    return v;
}
__device__ __forceinline__ float warp_max(float v) {
#pragma unroll
    for (int o = 16; o > 0; o >>= 1) v = fmaxf(v, __shfl_xor_sync(0xffffffffu, v, o));
    return v;
}
__device__ __forceinline__ float dot4(float4 a, float4 b) {
    return a.x * b.x + a.y * b.y + a.z * b.z + a.w * b.w;
}

// Cross-warp reduction of 8 per-row partials (one per thread, 256 threads).
// After warp_sum, lane0 of each of the 8 warps holds partial for rows 0..7.
// Final: threads 0..63 combine; thread with (t&7)==0 holds row t>>3 result.
// Returns result (valid where (t&7)==0), row index via *rowp.
__device__ __forceinline__ float reduce_rows8(float p[8], float* sm, int* rowp) {
    int lane = threadIdx.x & 31, wid = threadIdx.x >> 5;
#pragma unroll
    for (int r = 0; r < 8; r++) {
        float v = warp_sum(p[r]);
        if (lane == 0) sm[r * 8 + wid] = v;
    }
    __syncthreads();
    float v = 0.f;
    int t = threadIdx.x;
    if (t < 64) {
        v = sm[t];
#pragma unroll
        for (int o = 4; o > 0; o >>= 1) v += __shfl_xor_sync(0xffffffffu, v, o, 8);
    }
    *rowp = t >> 3;
    return v;
}

// K1: query = W_attn @ u_t. 128 blocks x 8 rows. Blocks 0..3 zero g_context.
__global__ void k_query(const float* __restrict__ W_attn, const float* __restrict__ u_t) {
    __shared__ float sm[64];
    if (blockIdx.x < 4) g_context[blockIdx.x * 256 + threadIdx.x] = 0.f;

    int t = threadIdx.x;
    const float4* u4 = (const float4*)u_t;
    float4 b = u4[t];                 // thread's 4 columns, reused for 8 rows
    int row0 = blockIdx.x * 8;
    float p[8];
#pragma unroll
    for (int r = 0; r < 8; r++) {
        const float4* w = (const float4*)(W_attn + (size_t)(row0 + r) * HID);
        p[r] = dot4(__ldcs(&w[t]), b);
    }
    int rr;
    float v = reduce_rows8(p, sm, &rr);
    if (t < 64 && (t & 7) == 0) g_query[row0 + rr] = v;
}

// K2: FUSED single pass over the bank: copy + logits + online-softmax context.
__global__ void __launch_bounds__(256, 2)
k_fused(const float* __restrict__ SE, float* __restrict__ out) {
    __shared__ float q[HID];
    for (int i = threadIdx.x; i < HID; i += blockDim.x) q[i] = g_query[i];
    __syncthreads();

    int warp = threadIdx.x >> 5, lane = threadIdx.x & 31;
    int w = blockIdx.x * 8 + warp;
    size_t base = (size_t)w * ROWS_PER_WARP * (HID / 4);   // float4 units

    const float4* se4  = (const float4*)SE;
    float4*       out4 = (float4*)out;
    const float4* q4   = (const float4*)q;

    float4 v0[8], v1[8], acc[8];
#pragma unroll
    for (int k = 0; k < 8; k++) acc[k] = make_float4(0.f, 0.f, 0.f, 0.f);
    float m = -INFINITY, s = 0.f;

#pragma unroll
    for (int k = 0; k < 8; k++) v0[k] = __ldcs(&se4[base + k * 32 + lane]);

    for (int r = 0; r < ROWS_PER_WARP; r++) {
        size_t rb = base + (size_t)r * (HID / 4);
        if (r + 1 < ROWS_PER_WARP) {
#pragma unroll
            for (int k = 0; k < 8; k++) v1[k] = __ldcs(&se4[rb + (HID / 4) + k * 32 + lane]);
        }
        float p = 0.f;
#pragma unroll
        for (int k = 0; k < 8; k++) p += dot4(v0[k], q4[k * 32 + lane]);
        p = warp_sum(p);

        float mn = fmaxf(m, p);
        float sc = expf(m - mn);        // first iter: exp(-inf)=0
        float wt = expf(p - mn);
        s = s * sc + wt;
        m = mn;
#pragma unroll
        for (int k = 0; k < 8; k++) {
            __stcs(&out4[rb + k * 32 + lane], v0[k]);
            acc[k].x = fmaf(acc[k].x, sc, wt * v0[k].x);
            acc[k].y = fmaf(acc[k].y, sc, wt * v0[k].y);
            acc[k].z = fmaf(acc[k].z, sc, wt * v0[k].z);
            acc[k].w = fmaf(acc[k].w, sc, wt * v0[k].w);
        }
#pragma unroll
        for (int k = 0; k < 8; k++) v0[k] = v1[k];
    }

    if (lane == 0) { g_wm[w] = m; g_ws[w] = s; }
    float4* vp = (float4*)g_wv + (size_t)w * (HID / 4);
#pragma unroll
    for (int k = 0; k < 8; k++) vp[k * 32 + lane] = acc[k];
}

// K3: combine 2048 per-warp partials -> g_context.
// 64 blocks; each block redundantly computes global M,S, reduces 32 partial
// vectors, atomically adds (64 atomics per address).
__global__ void k_ctx() {
    __shared__ float sm[32];
    __shared__ float sM, sS;
    __shared__ float e[32];
    int t = threadIdx.x;
    int lane = t & 31, wid = t >> 5;

    float mv[8];
#pragma unroll
    for (int j = 0; j < 8; j++) mv[j] = g_wm[t + 256 * j];
    float m = mv[0];
#pragma unroll
    for (int j = 1; j < 8; j++) m = fmaxf(m, mv[j]);
    m = warp_max(m);
    if (lane == 0) sm[wid] = m;
    __syncthreads();
    if (t < 32) {
        float x = (t < 8) ? sm[t] : -INFINITY;
        x = warp_max(x);
        if (t == 0) sM = x;
    }
    __syncthreads();
    float M = sM;

    float ss = 0.f;
#pragma unroll
    for (int j = 0; j < 8; j++) ss += g_ws[t + 256 * j] * expf(mv[j] - M);
    ss = warp_sum(ss);
    __syncthreads();
    if (lane == 0) sm[wid] = ss;
    __syncthreads();
    if (t < 32) {
        float x = (t < 8) ? sm[t] : 0.f;
        x = warp_sum(x);
        if (t == 0) sS = x;
    }
    __syncthreads();
    float invS = 1.f / sS;

    int wbase = blockIdx.x * 32;
    if (t < 32) e[t] = expf(g_wm[wbase + t] - M) * invS;
    __syncthreads();

    const float4* v4 = (const float4*)g_wv;
    float4 acc = make_float4(0.f, 0.f, 0.f, 0.f);
#pragma unroll 8
    for (int j = 0; j < 32; j++) {
        float4 v = __ldcs(&v4[(size_t)(wbase + j) * (HID / 4) + t]);
        float ee = e[j];
        acc.x = fmaf(ee, v.x, acc.x);
        acc.y = fmaf(ee, v.y, acc.y);
        acc.z = fmaf(ee, v.z, acc.z);
        acc.w = fmaf(ee, v.w, acc.w);
    }
    float* ctx = g_context + t * 4;
    atomicAdd(ctx + 0, acc.x);
    atomicAdd(ctx + 1, acc.y);
    atomicAdd(ctx + 2, acc.z);
    atomicAdd(ctx + 3, acc.w);
}

// K4: h = gelu(W1 @ um + b1). 256 blocks x 8 rows each.
// um float4s cached in registers, reused across the 8 rows -> 24 independent
// LDGs per thread per block.
__global__ void k_h(const float* __restrict__ W1, const float* __restrict__ b1,
                    const float* __restrict__ u_t, const float* __restrict__ SE,
                    const int* __restrict__ s_i_p) {
    __shared__ float um[UMAT];
    __shared__ float sm[64];
    int si = *s_i_p;
    for (int i = threadIdx.x; i < UMAT; i += blockDim.x) {
        float v;
        if (i < 1024)      v = u_t[i];
        else if (i < 2048) v = SE[(size_t)si * HID + (i - 1024)];
        else               v = g_context[i - 2048];
        um[i] = v;
    }
    __syncthreads();

    int t = threadIdx.x;
    const float4* u4 = (const float4*)um;
    float4 b0 = u4[t], b1v = u4[t + 256], b2v = u4[t + 512];

    int row0 = blockIdx.x * 8;
    float p[8];
#pragma unroll
    for (int r = 0; r < 8; r++) {
        const float4* w = (const float4*)(W1 + (size_t)(row0 + r) * UMAT);
        float4 a0 = __ldcs(&w[t]);
        float4 a1 = __ldcs(&w[t + 256]);
        float4 a2 = __ldcs(&w[t + 512]);
        p[r] = dot4(a0, b0) + dot4(a1, b1v) + dot4(a2, b2v);
    }
    int rr;
    float v = reduce_rows8(p, sm, &rr);
    if (t < 64 && (t & 7) == 0) {
        int row = row0 + rr;
        float x = v + b1[row];
        g_hmid[row] = 0.5f * x * (1.f + erff(x * 0.70710678118654752f));
    }
}

// K5: o = W2 @ h + b2. 128 blocks x 8 rows each.
__global__ void k_o(const float* __restrict__ W2, const float* __restrict__ b2) {
    __shared__ float h[DUP];
    __shared__ float sm[64];
    for (int i = threadIdx.x; i < DUP; i += blockDim.x) h[i] = g_hmid[i];
    __syncthreads();

    int t = threadIdx.x;
    const float4* h4 = (const float4*)h;
    float4 b0 = h4[t], b1v = h4[t + 256];

    int row0 = blockIdx.x * 8;
    float p[8];
#pragma unroll
    for (int r = 0; r < 8; r++) {
        const float4* w = (const float4*)(W2 + (size_t)(row0 + r) * DUP);
        float4 a0 = __ldcs(&w[t]);
        float4 a1 = __ldcs(&w[t + 256]);
        p[r] = dot4(a0, b0) + dot4(a1, b1v);
    }
    int rr;
    float v = reduce_rows8(p, sm, &rr);
    if (t < 64 && (t & 7) == 0) {
        int row = row0 + rr;
        g_ovec[row] = v + b2[row];
    }
}

// K6: LayerNorm over o + residual scatter of row s_i (single block, 1024 threads)
__global__ void k_ln_scatter(const float* __restrict__ SE,
                             const float* __restrict__ gamma,
                             const float* __restrict__ beta,
                             const int* __restrict__ s_i_p,
                             float* __restrict__ out) {
    __shared__ float sm[32];
    __shared__ float s_mu, s_rstd;
    int t = threadIdx.x;
    float o = g_ovec[t];

    float v = warp_sum(o);
    if ((t & 31) == 0) sm[t >> 5] = v;
    __syncthreads();
    if (t < 32) {
        v = warp_sum(sm[t]);
        if (t == 0) s_mu = v * (1.f / 1024.f);
    }
    __syncthreads();

    float d = o - s_mu;
    v = warp_sum(d * d);
    __syncthreads();
    if ((t & 31) == 0) sm[t >> 5] = v;
    __syncthreads();
    if (t < 32) {
        v = warp_sum(sm[t]);
        if (t == 0) s_rstd = rsqrtf(v * (1.f / 1024.f) + LN_EPS);
    }
    __syncthreads();

    int si = *s_i_p;
    float hs = SE[(size_t)si * HID + t];
    out[(size_t)si * HID + t] = hs + d * s_rstd * gamma[t] + beta[t];
}

extern "C" void kernel_launch(void* const* d_in, const int* in_sizes, int n_in,
                              void* d_out, int out_size) {
    const float* u_t    = (const float*)d_in[0];
    const float* SE     = (const float*)d_in[1];
    const float* W_attn = (const float*)d_in[2];
    const float* W1     = (const float*)d_in[3];
    const float* b1     = (const float*)d_in[4];
    const float* W2     = (const float*)d_in[5];
    const float* b2     = (const float*)d_in[6];
    const float* gamma  = (const float*)d_in[7];
    const float* beta   = (const float*)d_in[8];
    const int*   s_i    = (const int*)d_in[9];
    float* out = (float*)d_out;

    k_query<<<HID / 8, 256>>>(W_attn, u_t);
    k_fused<<<FUSED_BLOCKS, 256>>>(SE, out);
    k_ctx<<<64, 256>>>();
    k_h<<<DUP / 8, 256>>>(W1, b1, u_t, SE, s_i);
    k_o<<<HID / 8, 256>>>(W2, b2);
    k_ln_scatter<<<1, 1024>>>(SE, gamma, beta, s_i, out);
}

// round 5
// speedup vs baseline: 1.7924x; 1.0408x over previous
#include <cuda_runtime.h>
#include <math.h>

#define N_SPK 65536
#define HID   1024
#define DUP   2048
#define UMAT  3072
#define LN_EPS 1e-5f

#define ROWS_PER_WARP 32
#define WARPS_TOTAL   (N_SPK / ROWS_PER_WARP)    // 2048
#define FUSED_BLOCKS  (WARPS_TOTAL / 8)           // 256 blocks x 8 warps

// ---- scratch (allocation-free: __device__ globals) ----
__device__ float g_query[HID];
__device__ float g_wm[WARPS_TOTAL];               // per-warp running max
__device__ float g_ws[WARPS_TOTAL];               // per-warp running sum
__device__ float g_wv[WARPS_TOTAL * HID];         // per-warp weighted vectors (8 MB)
__device__ float g_context[HID];
__device__ float g_hacc[DUP];                     // split-K partial sums for layer 1
__device__ float g_oacc[HID];                     // split-K partial sums for layer 2

__device__ __forceinline__ float warp_sum(float v) {
#pragma unroll
    for (int o = 16; o > 0; o >>= 1) v += __shfl_xor_sync(0xffffffffu, v, o);
    return v;
}
__device__ __forceinline__ float warp_max(float v) {
#pragma unroll
    for (int o = 16; o > 0; o >>= 1) v = fmaxf(v, __shfl_xor_sync(0xffffffffu, v, o));
    return v;
}
__device__ __forceinline__ float dot4(float4 a, float4 b) {
    return a.x * b.x + a.y * b.y + a.z * b.z + a.w * b.w;
}

// Reduce 8 per-row partials held by all 256 threads. Result valid on threads
// t<64 with (t&7)==0, for row (t>>3).
__device__ __forceinline__ float reduce_rows8(float p[8], float* sm, int* rowp) {
    int lane = threadIdx.x & 31, wid = threadIdx.x >> 5;
#pragma unroll
    for (int r = 0; r < 8; r++) {
        float v = warp_sum(p[r]);
        if (lane == 0) sm[r * 8 + wid] = v;
    }
    __syncthreads();
    float v = 0.f;
    int t = threadIdx.x;
    if (t < 64) {
        v = sm[t];
#pragma unroll
        for (int o = 4; o > 0; o >>= 1) v += __shfl_xor_sync(0xffffffffu, v, o, 8);
    }
    *rowp = t >> 3;
    return v;
}

// K1: query = W_attn @ u_t (128 blocks x 8 rows). Also zeros accumulators.
__global__ void k_query(const float* __restrict__ W_attn, const float* __restrict__ u_t) {
    __shared__ float sm[64];
    int gt = blockIdx.x * 256 + threadIdx.x;
    if (gt < HID)  g_context[gt] = 0.f;
    if (gt < DUP)  g_hacc[gt] = 0.f;
    if (gt < HID)  g_oacc[gt] = 0.f;

    int t = threadIdx.x;
    const float4* u4 = (const float4*)u_t;
    float4 b = u4[t];
    int row0 = blockIdx.x * 8;
    float p[8];
#pragma unroll
    for (int r = 0; r < 8; r++) {
        const float4* w = (const float4*)(W_attn + (size_t)(row0 + r) * HID);
        p[r] = dot4(__ldcs(&w[t]), b);
    }
    int rr;
    float v = reduce_rows8(p, sm, &rr);
    if (t < 64 && (t & 7) == 0) g_query[row0 + rr] = v;
}

// K2: FUSED single pass over the bank: copy + logits + online-softmax context.
__global__ void __launch_bounds__(256, 2)
k_fused(const float* __restrict__ SE, float* __restrict__ out) {
    __shared__ float q[HID];
    for (int i = threadIdx.x; i < HID; i += blockDim.x) q[i] = g_query[i];
    __syncthreads();

    int warp = threadIdx.x >> 5, lane = threadIdx.x & 31;
    int w = blockIdx.x * 8 + warp;
    size_t base = (size_t)w * ROWS_PER_WARP * (HID / 4);

    const float4* se4  = (const float4*)SE;
    float4*       out4 = (float4*)out;
    const float4* q4   = (const float4*)q;

    float4 v0[8], v1[8], acc[8];
#pragma unroll
    for (int k = 0; k < 8; k++) acc[k] = make_float4(0.f, 0.f, 0.f, 0.f);
    float m = -INFINITY, s = 0.f;

#pragma unroll
    for (int k = 0; k < 8; k++) v0[k] = __ldcs(&se4[base + k * 32 + lane]);

    for (int r = 0; r < ROWS_PER_WARP; r++) {
        size_t rb = base + (size_t)r * (HID / 4);
        if (r + 1 < ROWS_PER_WARP) {
#pragma unroll
            for (int k = 0; k < 8; k++) v1[k] = __ldcs(&se4[rb + (HID / 4) + k * 32 + lane]);
        }
        float p = 0.f;
#pragma unroll
        for (int k = 0; k < 8; k++) p += dot4(v0[k], q4[k * 32 + lane]);
        p = warp_sum(p);

        float mn = fmaxf(m, p);
        float sc = expf(m - mn);
        float wt = expf(p - mn);
        s = s * sc + wt;
        m = mn;
#pragma unroll
        for (int k = 0; k < 8; k++) {
            __stcs(&out4[rb + k * 32 + lane], v0[k]);
            acc[k].x = fmaf(acc[k].x, sc, wt * v0[k].x);
            acc[k].y = fmaf(acc[k].y, sc, wt * v0[k].y);
            acc[k].z = fmaf(acc[k].z, sc, wt * v0[k].z);
            acc[k].w = fmaf(acc[k].w, sc, wt * v0[k].w);
        }
#pragma unroll
        for (int k = 0; k < 8; k++) v0[k] = v1[k];
    }

    if (lane == 0) { g_wm[w] = m; g_ws[w] = s; }
    float4* vp = (float4*)g_wv + (size_t)w * (HID / 4);
#pragma unroll
    for (int k = 0; k < 8; k++) vp[k * 32 + lane] = acc[k];
}

// K3: combine 2048 per-warp partials -> g_context (64 blocks, 64 atomics/addr).
__global__ void k_ctx() {
    __shared__ float sm[32];
    __shared__ float sM, sS;
    __shared__ float e[32];
    int t = threadIdx.x;
    int lane = t & 31, wid = t >> 5;

    float mv[8];
#pragma unroll
    for (int j = 0; j < 8; j++) mv[j] = g_wm[t + 256 * j];
    float m = mv[0];
#pragma unroll
    for (int j = 1; j < 8; j++) m = fmaxf(m, mv[j]);
    m = warp_max(m);
    if (lane == 0) sm[wid] = m;
    __syncthreads();
    if (t < 32) {
        float x = (t < 8) ? sm[t] : -INFINITY;
        x = warp_max(x);
        if (t == 0) sM = x;
    }
    __syncthreads();
    float M = sM;

    float ss = 0.f;
#pragma unroll
    for (int j = 0; j < 8; j++) ss += g_ws[t + 256 * j] * expf(mv[j] - M);
    ss = warp_sum(ss);
    __syncthreads();
    if (lane == 0) sm[wid] = ss;
    __syncthreads();
    if (t < 32) {
        float x = (t < 8) ? sm[t] : 0.f;
        x = warp_sum(x);
        if (t == 0) sS = x;
    }
    __syncthreads();
    float invS = 1.f / sS;

    int wbase = blockIdx.x * 32;
    if (t < 32) e[t] = expf(g_wm[wbase + t] - M) * invS;
    __syncthreads();

    const float4* v4 = (const float4*)g_wv;
    float4 acc = make_float4(0.f, 0.f, 0.f, 0.f);
#pragma unroll 8
    for (int j = 0; j < 32; j++) {
        float4 v = __ldcs(&v4[(size_t)(wbase + j) * (HID / 4) + t]);
        float ee = e[j];
        acc.x = fmaf(ee, v.x, acc.x);
        acc.y = fmaf(ee, v.y, acc.y);
        acc.z = fmaf(ee, v.z, acc.z);
        acc.w = fmaf(ee, v.w, acc.w);
    }
    float* ctx = g_context + t * 4;
    atomicAdd(ctx + 0, acc.x);
    atomicAdd(ctx + 1, acc.y);
    atomicAdd(ctx + 2, acc.z);
    atomicAdd(ctx + 3, acc.w);
}

// K4: split-K layer-1 partials. 768 blocks = 3 K-slices x 256 row-groups.
// Slice s covers um columns [s*1024, s*1024+1024):
//   s=0 -> u_t, s=1 -> SE[s_i], s=2 -> g_context.
// Per thread: ONE operand float4 in register + 8 independent W1 LDG.128s.
__global__ void k_h(const float* __restrict__ W1,
                    const float* __restrict__ u_t, const float* __restrict__ SE,
                    const int* __restrict__ s_i_p) {
    __shared__ float sm[64];
    int slice = blockIdx.x >> 8;          // 0..2
    int rg    = blockIdx.x & 255;         // 0..255
    int t = threadIdx.x;

    const float* src;
    if (slice == 0)      src = u_t;
    else if (slice == 1) src = SE + (size_t)(*s_i_p) * HID;
    else                 src = g_context;
    float4 b = ((const float4*)src)[t];

    int row0 = rg * 8;
    int coff = slice * 256 + t;           // float4 offset within W1 row
    float p[8];
#pragma unroll
    for (int r = 0; r < 8; r++) {
        const float4* w = (const float4*)(W1 + (size_t)(row0 + r) * UMAT);
        p[r] = dot4(__ldcs(&w[coff]), b);
    }
    int rr;
    float v = reduce_rows8(p, sm, &rr);
    if (t < 64 && (t & 7) == 0) atomicAdd(&g_hacc[row0 + rr], v);
}

// K5: split-K layer-2 partials. 256 blocks = 2 K-slices x 128 row-groups.
// Prologue: h_slice = gelu(g_hacc + b1) for this slice's 1024 columns.
__global__ void k_o(const float* __restrict__ W2, const float* __restrict__ b1) {
    __shared__ float h[HID];
    __shared__ float sm[64];
    int slice = blockIdx.x >> 7;          // 0..1
    int rg    = blockIdx.x & 127;         // 0..127
    int t = threadIdx.x;

    {
        float4 a = ((const float4*)g_hacc)[slice * 256 + t];
        float4 bb = ((const float4*)b1)[slice * 256 + t];
        float4 r;
        float x;
        x = a.x + bb.x; r.x = 0.5f * x * (1.f + erff(x * 0.70710678118654752f));
        x = a.y + bb.y; r.y = 0.5f * x * (1.f + erff(x * 0.70710678118654752f));
        x = a.z + bb.z; r.z = 0.5f * x * (1.f + erff(x * 0.70710678118654752f));
        x = a.w + bb.w; r.w = 0.5f * x * (1.f + erff(x * 0.70710678118654752f));
        ((float4*)h)[t] = r;
    }
    __syncthreads();

    float4 b = ((const float4*)h)[t];
    int row0 = rg * 8;
    int coff = slice * 256 + t;           // float4 offset within W2 row
    float p[8];
#pragma unroll
    for (int r = 0; r < 8; r++) {
        const float4* w = (const float4*)(W2 + (size_t)(row0 + r) * DUP);
        p[r] = dot4(__ldcs(&w[coff]), b);
    }
    int rr;
    float v = reduce_rows8(p, sm, &rr);
    if (t < 64 && (t & 7) == 0) atomicAdd(&g_oacc[row0 + rr], v);
}

// K6: LayerNorm over (g_oacc + b2) + residual scatter of row s_i.
__global__ void k_ln_scatter(const float* __restrict__ SE,
                             const float* __restrict__ b2,
                             const float* __restrict__ gamma,
                             const float* __restrict__ beta,
                             const int* __restrict__ s_i_p,
                             float* __restrict__ out) {
    __shared__ float sm[32];
    __shared__ float s_mu, s_rstd;
    int t = threadIdx.x;
    float o = g_oacc[t] + b2[t];

    float v = warp_sum(o);
    if ((t & 31) == 0) sm[t >> 5] = v;
    __syncthreads();
    if (t < 32) {
        v = warp_sum(sm[t]);
        if (t == 0) s_mu = v * (1.f / 1024.f);
    }
    __syncthreads();

    float d = o - s_mu;
    v = warp_sum(d * d);
    __syncthreads();
    if ((t & 31) == 0) sm[t >> 5] = v;
    __syncthreads();
    if (t < 32) {
        v = warp_sum(sm[t]);
        if (t == 0) s_rstd = rsqrtf(v * (1.f / 1024.f) + LN_EPS);
    }
    __syncthreads();

    int si = *s_i_p;
    float hs = SE[(size_t)si * HID + t];
    out[(size_t)si * HID + t] = hs + d * s_rstd * gamma[t] + beta[t];
}

extern "C" void kernel_launch(void* const* d_in, const int* in_sizes, int n_in,
                              void* d_out, int out_size) {
    const float* u_t    = (const float*)d_in[0];
    const float* SE     = (const float*)d_in[1];
    const float* W_attn = (const float*)d_in[2];
    const float* W1     = (const float*)d_in[3];
    const float* b1     = (const float*)d_in[4];
    const float* W2     = (const float*)d_in[5];
    const float* b2     = (const float*)d_in[6];
    const float* gamma  = (const float*)d_in[7];
    const float* beta   = (const float*)d_in[8];
    const int*   s_i    = (const int*)d_in[9];
    float* out = (float*)d_out;

    k_query<<<HID / 8, 256>>>(W_attn, u_t);
    k_fused<<<FUSED_BLOCKS, 256>>>(SE, out);
    k_ctx<<<64, 256>>>();
    k_h<<<3 * 256, 256>>>(W1, u_t, SE, s_i);
    k_o<<<2 * 128, 256>>>(W2, b1);
    k_ln_scatter<<<1, 1024>>>(SE, b2, gamma, beta, s_i, out);
}

// round 6
// speedup vs baseline: 1.8023x; 1.0055x over previous
#include <cuda_runtime.h>
#include <math.h>

#define N_SPK 65536
#define HID   1024
#define DUP   2048
#define UMAT  3072
#define LN_EPS 1e-5f

#define FUSED_BLOCKS 296                 // 148 SMs x 2 resident blocks
#define WARPS_TOTAL  (FUSED_BLOCKS * 8)  // 2368 persistent warps
#define CTX_BLOCKS   (WARPS_TOTAL / 32)  // 74

// ---- scratch (allocation-free: __device__ globals) ----
__device__ float g_query[HID];
__device__ float g_wm[WARPS_TOTAL];               // per-warp running max
__device__ float g_ws[WARPS_TOTAL];               // per-warp running sum
__device__ float g_wv[WARPS_TOTAL * HID];         // per-warp weighted vectors (~9.7 MB)
__device__ float g_context[HID];
__device__ float g_hacc[DUP];                     // split-K partials, layer 1
__device__ float g_oacc[HID];                     // split-K partials, layer 2

__device__ __forceinline__ float warp_sum(float v) {
#pragma unroll
    for (int o = 16; o > 0; o >>= 1) v += __shfl_xor_sync(0xffffffffu, v, o);
    return v;
}
__device__ __forceinline__ float warp_max(float v) {
#pragma unroll
    for (int o = 16; o > 0; o >>= 1) v = fmaxf(v, __shfl_xor_sync(0xffffffffu, v, o));
    return v;
}
__device__ __forceinline__ float dot4(float4 a, float4 b) {
    return a.x * b.x + a.y * b.y + a.z * b.z + a.w * b.w;
}

// K1: query = W_attn @ u_t (128 blocks x 8 rows). Also zeros accumulators.
__global__ void k_query(const float* __restrict__ W_attn, const float* __restrict__ u_t) {
    __shared__ float sm[64];
    int gt = blockIdx.x * 256 + threadIdx.x;
    if (gt < HID) g_context[gt] = 0.f;
    if (gt < DUP) g_hacc[gt] = 0.f;
    if (gt < HID) g_oacc[gt] = 0.f;

    int t = threadIdx.x;
    int lane = t & 31, wid = t >> 5;
    const float4* u4 = (const float4*)u_t;
    float4 b = u4[t];
    int row0 = blockIdx.x * 8;
    float p[8];
#pragma unroll
    for (int r = 0; r < 8; r++) {
        const float4* w = (const float4*)(W_attn + (size_t)(row0 + r) * HID);
        p[r] = dot4(__ldcs(&w[t]), b);
    }
#pragma unroll
    for (int r = 0; r < 8; r++) {
        float v = warp_sum(p[r]);
        if (lane == 0) sm[r * 8 + wid] = v;
    }
    __syncthreads();
    if (t < 64) {
        float v = sm[t];
#pragma unroll
        for (int o = 4; o > 0; o >>= 1) v += __shfl_xor_sync(0xffffffffu, v, o, 8);
        if ((t & 7) == 0) g_query[row0 + (t >> 3)] = v;
    }
}

// K2: FUSED balanced persistent pass: copy + logits + online-softmax context.
// 296 blocks x 8 warps; each warp row-strides with stride 2368 (27-28 rows).
__global__ void __launch_bounds__(256, 2)
k_fused(const float* __restrict__ SE, float* __restrict__ out) {
    __shared__ float q[HID];
    for (int i = threadIdx.x; i < HID; i += blockDim.x) q[i] = g_query[i];
    __syncthreads();

    int warp = threadIdx.x >> 5, lane = threadIdx.x & 31;
    int gw = blockIdx.x * 8 + warp;

    const float4* se4  = (const float4*)SE;
    float4*       out4 = (float4*)out;
    const float4* q4   = (const float4*)q;

    float4 v0[8], v1[8], acc[8];
#pragma unroll
    for (int k = 0; k < 8; k++) acc[k] = make_float4(0.f, 0.f, 0.f, 0.f);
    float m = -INFINITY, s = 0.f;

    // first row load (gw < 2368 <= N_SPK always)
    {
        size_t rb = (size_t)gw * (HID / 4);
#pragma unroll
        for (int k = 0; k < 8; k++) v0[k] = __ldcs(&se4[rb + k * 32 + lane]);
    }

    for (int row = gw; row < N_SPK; row += WARPS_TOTAL) {
        size_t rb = (size_t)row * (HID / 4);
        int nrow = row + WARPS_TOTAL;
        if (nrow < N_SPK) {
            size_t nb = (size_t)nrow * (HID / 4);
#pragma unroll
            for (int k = 0; k < 8; k++) v1[k] = __ldcs(&se4[nb + k * 32 + lane]);
        }
        float p = 0.f;
#pragma unroll
        for (int k = 0; k < 8; k++) p += dot4(v0[k], q4[k * 32 + lane]);
        p = warp_sum(p);

        float mn = fmaxf(m, p);
        float sc = expf(m - mn);        // first iter: exp(-inf)=0
        float wt = expf(p - mn);
        s = s * sc + wt;
        m = mn;
#pragma unroll
        for (int k = 0; k < 8; k++) {
            __stcs(&out4[rb + k * 32 + lane], v0[k]);
            acc[k].x = fmaf(acc[k].x, sc, wt * v0[k].x);
            acc[k].y = fmaf(acc[k].y, sc, wt * v0[k].y);
            acc[k].z = fmaf(acc[k].z, sc, wt * v0[k].z);
            acc[k].w = fmaf(acc[k].w, sc, wt * v0[k].w);
        }
#pragma unroll
        for (int k = 0; k < 8; k++) v0[k] = v1[k];
    }

    if (lane == 0) { g_wm[gw] = m; g_ws[gw] = s; }
    float4* vp = (float4*)g_wv + (size_t)gw * (HID / 4);
#pragma unroll
    for (int k = 0; k < 8; k++) vp[k * 32 + lane] = acc[k];
}

// K3: combine 2368 per-warp partials -> g_context (74 blocks x 32 partials).
__global__ void k_ctx() {
    __shared__ float sm[32];
    __shared__ float sM, sS;
    __shared__ float e[32];
    int t = threadIdx.x;
    int lane = t & 31, wid = t >> 5;

    // global max over 2368 warp maxima
    float mv[10];
#pragma unroll
    for (int j = 0; j < 10; j++) {
        int idx = t + 256 * j;
        mv[j] = (idx < WARPS_TOTAL) ? g_wm[idx] : -INFINITY;
    }
    float m = mv[0];
#pragma unroll
    for (int j = 1; j < 10; j++) m = fmaxf(m, mv[j]);
    m = warp_max(m);
    if (lane == 0) sm[wid] = m;
    __syncthreads();
    if (t < 32) {
        float x = (t < 8) ? sm[t] : -INFINITY;
        x = warp_max(x);
        if (t == 0) sM = x;
    }
    __syncthreads();
    float M = sM;

    // global sum
    float ss = 0.f;
#pragma unroll
    for (int j = 0; j < 10; j++) {
        int idx = t + 256 * j;
        if (idx < WARPS_TOTAL) ss += g_ws[idx] * expf(mv[j] - M);
    }
    ss = warp_sum(ss);
    __syncthreads();
    if (lane == 0) sm[wid] = ss;
    __syncthreads();
    if (t < 32) {
        float x = (t < 8) ? sm[t] : 0.f;
        x = warp_sum(x);
        if (t == 0) sS = x;
    }
    __syncthreads();
    float invS = 1.f / sS;

    int wbase = blockIdx.x * 32;
    if (t < 32) e[t] = expf(g_wm[wbase + t] - M) * invS;
    __syncthreads();

    const float4* v4 = (const float4*)g_wv;
    float4 acc = make_float4(0.f, 0.f, 0.f, 0.f);
#pragma unroll 8
    for (int j = 0; j < 32; j++) {
        float4 v = __ldcs(&v4[(size_t)(wbase + j) * (HID / 4) + t]);
        float ee = e[j];
        acc.x = fmaf(ee, v.x, acc.x);
        acc.y = fmaf(ee, v.y, acc.y);
        acc.z = fmaf(ee, v.z, acc.z);
        acc.w = fmaf(ee, v.w, acc.w);
    }
    float* ctx = g_context + t * 4;
    atomicAdd(ctx + 0, acc.x);
    atomicAdd(ctx + 1, acc.y);
    atomicAdd(ctx + 2, acc.z);
    atomicAdd(ctx + 3, acc.w);
}

// K4: split-K layer-1 partials. 384 blocks = 3 K-slices x 128 groups of 16 rows.
// Per thread: ONE operand float4 + 16 independent W1 LDG.128s (MLP 16).
__global__ void __launch_bounds__(256)
k_h(const float* __restrict__ W1,
    const float* __restrict__ u_t, const float* __restrict__ SE,
    const int* __restrict__ s_i_p) {
    __shared__ float sm[128];
    int slice = blockIdx.x >> 7;          // 0..2
    int rg    = blockIdx.x & 127;         // 0..127
    int t = threadIdx.x;
    int lane = t & 31, wid = t >> 5;

    const float* src;
    if (slice == 0)      src = u_t;
    else if (slice == 1) src = SE + (size_t)(*s_i_p) * HID;
    else                 src = g_context;
    float4 b = ((const float4*)src)[t];

    int row0 = rg * 16;
    int coff = slice * 256 + t;
    float p[16];
#pragma unroll
    for (int r = 0; r < 16; r++) {
        const float4* w = (const float4*)(W1 + (size_t)(row0 + r) * UMAT);
        p[r] = dot4(__ldcs(&w[coff]), b);
    }
#pragma unroll
    for (int r = 0; r < 16; r++) {
        float v = warp_sum(p[r]);
        if (lane == 0) sm[r * 8 + wid] = v;
    }
    __syncthreads();
    if (t < 128) {
        float v = sm[t];
#pragma unroll
        for (int o = 4; o > 0; o >>= 1) v += __shfl_xor_sync(0xffffffffu, v, o, 8);
        if ((t & 7) == 0) atomicAdd(&g_hacc[row0 + (t >> 3)], v);
    }
}

// K5: split-K layer-2 partials. 256 blocks = 2 K-slices x 128 groups of 8 rows.
__global__ void k_o(const float* __restrict__ W2, const float* __restrict__ b1) {
    __shared__ float h[HID];
    __shared__ float sm[64];
    int slice = blockIdx.x >> 7;          // 0..1
    int rg    = blockIdx.x & 127;         // 0..127
    int t = threadIdx.x;
    int lane = t & 31, wid = t >> 5;

    {
        float4 a = ((const float4*)g_hacc)[slice * 256 + t];
        float4 bb = ((const float4*)b1)[slice * 256 + t];
        float4 r;
        float x;
        x = a.x + bb.x; r.x = 0.5f * x * (1.f + erff(x * 0.70710678118654752f));
        x = a.y + bb.y; r.y = 0.5f * x * (1.f + erff(x * 0.70710678118654752f));
        x = a.z + bb.z; r.z = 0.5f * x * (1.f + erff(x * 0.70710678118654752f));
        x = a.w + bb.w; r.w = 0.5f * x * (1.f + erff(x * 0.70710678118654752f));
        ((float4*)h)[t] = r;
    }
    __syncthreads();

    float4 b = ((const float4*)h)[t];
    int row0 = rg * 8;
    int coff = slice * 256 + t;
    float p[8];
#pragma unroll
    for (int r = 0; r < 8; r++) {
        const float4* w = (const float4*)(W2 + (size_t)(row0 + r) * DUP);
        p[r] = dot4(__ldcs(&w[coff]), b);
    }
#pragma unroll
    for (int r = 0; r < 8; r++) {
        float v = warp_sum(p[r]);
        if (lane == 0) sm[r * 8 + wid] = v;
    }
    __syncthreads();
    if (t < 64) {
        float v = sm[t];
#pragma unroll
        for (int o = 4; o > 0; o >>= 1) v += __shfl_xor_sync(0xffffffffu, v, o, 8);
        if ((t & 7) == 0) atomicAdd(&g_oacc[row0 + (t >> 3)], v);
    }
}

// K6: LayerNorm over (g_oacc + b2) + residual scatter of row s_i.
__global__ void k_ln_scatter(const float* __restrict__ SE,
                             const float* __restrict__ b2,
                             const float* __restrict__ gamma,
                             const float* __restrict__ beta,
                             const int* __restrict__ s_i_p,
                             float* __restrict__ out) {
    __shared__ float sm[32];
    __shared__ float s_mu, s_rstd;
    int t = threadIdx.x;
    float o = g_oacc[t] + b2[t];

    float v = warp_sum(o);
    if ((t & 31) == 0) sm[t >> 5] = v;
    __syncthreads();
    if (t < 32) {
        v = warp_sum(sm[t]);
        if (t == 0) s_mu = v * (1.f / 1024.f);
    }
    __syncthreads();

    float d = o - s_mu;
    v = warp_sum(d * d);
    __syncthreads();
    if ((t & 31) == 0) sm[t >> 5] = v;
    __syncthreads();
    if (t < 32) {
        v = warp_sum(sm[t]);
        if (t == 0) s_rstd = rsqrtf(v * (1.f / 1024.f) + LN_EPS);
    }
    __syncthreads();

    int si = *s_i_p;
    float hs = SE[(size_t)si * HID + t];
    out[(size_t)si * HID + t] = hs + d * s_rstd * gamma[t] + beta[t];
}

extern "C" void kernel_launch(void* const* d_in, const int* in_sizes, int n_in,
                              void* d_out, int out_size) {
    const float* u_t    = (const float*)d_in[0];
    const float* SE     = (const float*)d_in[1];
    const float* W_attn = (const float*)d_in[2];
    const float* W1     = (const float*)d_in[3];
    const float* b1     = (const float*)d_in[4];
    const float* W2     = (const float*)d_in[5];
    const float* b2     = (const float*)d_in[6];
    const float* gamma  = (const float*)d_in[7];
    const float* beta   = (const float*)d_in[8];
    const int*   s_i    = (const int*)d_in[9];
    float* out = (float*)d_out;

    k_query<<<HID / 8, 256>>>(W_attn, u_t);
    k_fused<<<FUSED_BLOCKS, 256>>>(SE, out);
    k_ctx<<<CTX_BLOCKS, 256>>>();
    k_h<<<3 * 128, 256>>>(W1, u_t, SE, s_i);
    k_o<<<2 * 128, 256>>>(W2, b1);
    k_ln_scatter<<<1, 1024>>>(SE, b2, gamma, beta, s_i, out);
}

// round 7
// speedup vs baseline: 1.8919x; 1.0497x over previous
#include <cuda_runtime.h>
#include <math.h>

#define N_SPK 65536
#define HID   1024
#define DUP   2048
#define UMAT  3072
#define LN_EPS 1e-5f

#define FUSED_BLOCKS 296                 // 148 SMs x 2 resident blocks
#define WARPS_TOTAL  (FUSED_BLOCKS * 8)  // 2368 persistent warps
#define CTX_BLOCKS   (FUSED_BLOCKS / 8)  // 37 blocks x 8 partials

// ---- scratch (allocation-free: __device__ globals) ----
__device__ float g_query[HID];
__device__ float g_wm[FUSED_BLOCKS];              // per-BLOCK softmax max
__device__ float g_ws[FUSED_BLOCKS];              // per-BLOCK softmax sum
__device__ float g_wv[FUSED_BLOCKS * HID];        // per-BLOCK weighted vectors (1.2 MB)
__device__ float g_context[HID];
__device__ float g_hacc[DUP];                     // split-K partials, layer 1
__device__ float g_oacc[HID];                     // split-K partials, layer 2

__device__ __forceinline__ float warp_sum(float v) {
#pragma unroll
    for (int o = 16; o > 0; o >>= 1) v += __shfl_xor_sync(0xffffffffu, v, o);
    return v;
}
__device__ __forceinline__ float warp_max(float v) {
#pragma unroll
    for (int o = 16; o > 0; o >>= 1) v = fmaxf(v, __shfl_xor_sync(0xffffffffu, v, o));
    return v;
}
__device__ __forceinline__ float dot4(float4 a, float4 b) {
    return a.x * b.x + a.y * b.y + a.z * b.z + a.w * b.w;
}

// K1: query = W_attn @ u_t (128 blocks x 8 rows). Also zeros accumulators.
__global__ void k_query(const float* __restrict__ W_attn, const float* __restrict__ u_t) {
    __shared__ float sm[64];
    int gt = blockIdx.x * 256 + threadIdx.x;
    if (gt < HID) g_context[gt] = 0.f;
    if (gt < DUP) g_hacc[gt] = 0.f;
    if (gt < HID) g_oacc[gt] = 0.f;

    int t = threadIdx.x;
    int lane = t & 31, wid = t >> 5;
    float4 b = ((const float4*)u_t)[t];
    int row0 = blockIdx.x * 8;

    float4 a[8];
#pragma unroll
    for (int r = 0; r < 8; r++)
        a[r] = __ldcs(&((const float4*)(W_attn + (size_t)(row0 + r) * HID))[t]);
    float p[8];
#pragma unroll
    for (int r = 0; r < 8; r++) p[r] = dot4(a[r], b);

#pragma unroll
    for (int r = 0; r < 8; r++) {
        float v = warp_sum(p[r]);
        if (lane == 0) sm[r * 8 + wid] = v;
    }
    __syncthreads();
    if (t < 64) {
        float v = sm[t];
#pragma unroll
        for (int o = 4; o > 0; o >>= 1) v += __shfl_xor_sync(0xffffffffu, v, o, 8);
        if ((t & 7) == 0) g_query[row0 + (t >> 3)] = v;
    }
}

// K2: FUSED balanced persistent pass: copy + logits + online-softmax context.
// 296 blocks x 8 warps; warps stride the bank; block merges its 8 warp
// partials in smem and emits ONE (m, s, vec) partial.
__global__ void __launch_bounds__(256, 2)
k_fused(const float* __restrict__ SE, float* __restrict__ out) {
    __shared__ float q[HID];
    __shared__ float s_acc[HID];
    __shared__ float s_m[8], s_s[8];
    for (int i = threadIdx.x; i < HID; i += blockDim.x) q[i] = g_query[i];
    __syncthreads();

    int warp = threadIdx.x >> 5, lane = threadIdx.x & 31;
    int gw = blockIdx.x * 8 + warp;

    const float4* se4  = (const float4*)SE;
    float4*       out4 = (float4*)out;
    const float4* q4   = (const float4*)q;

    float4 v0[8], v1[8], acc[8];
#pragma unroll
    for (int k = 0; k < 8; k++) acc[k] = make_float4(0.f, 0.f, 0.f, 0.f);
    float m = -INFINITY, s = 0.f;

    {
        size_t rb = (size_t)gw * (HID / 4);
#pragma unroll
        for (int k = 0; k < 8; k++) v0[k] = __ldcs(&se4[rb + k * 32 + lane]);
    }

    for (int row = gw; row < N_SPK; row += WARPS_TOTAL) {
        size_t rb = (size_t)row * (HID / 4);
        int nrow = row + WARPS_TOTAL;
        if (nrow < N_SPK) {
            size_t nb = (size_t)nrow * (HID / 4);
#pragma unroll
            for (int k = 0; k < 8; k++) v1[k] = __ldcs(&se4[nb + k * 32 + lane]);
        }
        float p = 0.f;
#pragma unroll
        for (int k = 0; k < 8; k++) p += dot4(v0[k], q4[k * 32 + lane]);
        p = warp_sum(p);

        float mn = fmaxf(m, p);
        float sc = expf(m - mn);        // first iter: exp(-inf)=0
        float wt = expf(p - mn);
        s = s * sc + wt;
        m = mn;
#pragma unroll
        for (int k = 0; k < 8; k++) {
            __stcs(&out4[rb + k * 32 + lane], v0[k]);
            acc[k].x = fmaf(acc[k].x, sc, wt * v0[k].x);
            acc[k].y = fmaf(acc[k].y, sc, wt * v0[k].y);
            acc[k].z = fmaf(acc[k].z, sc, wt * v0[k].z);
            acc[k].w = fmaf(acc[k].w, sc, wt * v0[k].w);
        }
#pragma unroll
        for (int k = 0; k < 8; k++) v0[k] = v1[k];
    }

    // ---- block-level merge of 8 warp partials ----
    if (lane == 0) { s_m[warp] = m; s_s[warp] = s; }
    __syncthreads();
    float Mb = s_m[0];
#pragma unroll
    for (int j = 1; j < 8; j++) Mb = fmaxf(Mb, s_m[j]);
    float Sb = 0.f;
#pragma unroll
    for (int j = 0; j < 8; j++) Sb += s_s[j] * expf(s_m[j] - Mb);
    float scw = expf(m - Mb);

    float4* sa4 = (float4*)s_acc;
    for (int w = 0; w < 8; w++) {
        if (warp == w) {
#pragma unroll
            for (int k = 0; k < 8; k++) {
                int c = k * 32 + lane;
                float4 r;
                if (w == 0) r = make_float4(0.f, 0.f, 0.f, 0.f);
                else        r = sa4[c];
                r.x += acc[k].x * scw;
                r.y += acc[k].y * scw;
                r.z += acc[k].z * scw;
                r.w += acc[k].w * scw;
                sa4[c] = r;
            }
        }
        __syncthreads();
    }

    if (threadIdx.x == 0) { g_wm[blockIdx.x] = Mb; g_ws[blockIdx.x] = Sb; }
    ((float4*)g_wv)[(size_t)blockIdx.x * (HID / 4) + threadIdx.x] = sa4[threadIdx.x];
}

// K3: combine 296 per-block partials -> g_context (37 blocks x 8 partials).
__global__ void k_ctx() {
    __shared__ float sm[32];
    __shared__ float sM, sS;
    __shared__ float e[8];
    int t = threadIdx.x;
    int lane = t & 31, wid = t >> 5;

    float m0 = (t < FUSED_BLOCKS) ? g_wm[t] : -INFINITY;
    float m1 = (t + 256 < FUSED_BLOCKS) ? g_wm[t + 256] : -INFINITY;
    float m = fmaxf(m0, m1);
    m = warp_max(m);
    if (lane == 0) sm[wid] = m;
    __syncthreads();
    if (t < 32) {
        float x = (t < 8) ? sm[t] : -INFINITY;
        x = warp_max(x);
        if (t == 0) sM = x;
    }
    __syncthreads();
    float M = sM;

    float ss = 0.f;
    if (t < FUSED_BLOCKS)       ss += g_ws[t] * expf(m0 - M);
    if (t + 256 < FUSED_BLOCKS) ss += g_ws[t + 256] * expf(m1 - M);
    ss = warp_sum(ss);
    __syncthreads();
    if (lane == 0) sm[wid] = ss;
    __syncthreads();
    if (t < 32) {
        float x = (t < 8) ? sm[t] : 0.f;
        x = warp_sum(x);
        if (t == 0) sS = x;
    }
    __syncthreads();
    float invS = 1.f / sS;

    int wbase = blockIdx.x * 8;
    if (t < 8) e[t] = expf(g_wm[wbase + t] - M) * invS;
    __syncthreads();

    const float4* v4 = (const float4*)g_wv;
    float4 acc = make_float4(0.f, 0.f, 0.f, 0.f);
#pragma unroll
    for (int j = 0; j < 8; j++) {
        float4 v = __ldcs(&v4[(size_t)(wbase + j) * (HID / 4) + t]);
        float ee = e[j];
        acc.x = fmaf(ee, v.x, acc.x);
        acc.y = fmaf(ee, v.y, acc.y);
        acc.z = fmaf(ee, v.z, acc.z);
        acc.w = fmaf(ee, v.w, acc.w);
    }
    float* ctx = g_context + t * 4;
    atomicAdd(ctx + 0, acc.x);
    atomicAdd(ctx + 1, acc.y);
    atomicAdd(ctx + 2, acc.z);
    atomicAdd(ctx + 3, acc.w);
}

// K4: split-K layer-1 partials. 384 blocks = 3 K-slices x 128 groups of 16 rows.
// Loads explicitly front-batched into a[16] (64 regs) -> real MLP 16.
__global__ void __launch_bounds__(256)
k_h(const float* __restrict__ W1,
    const float* __restrict__ u_t, const float* __restrict__ SE,
    const int* __restrict__ s_i_p) {
    __shared__ float sm[128];
    int slice = blockIdx.x >> 7;          // 0..2
    int rg    = blockIdx.x & 127;         // 0..127
    int t = threadIdx.x;
    int lane = t & 31, wid = t >> 5;

    const float* src;
    if (slice == 0)      src = u_t;
    else if (slice == 1) src = SE + (size_t)(*s_i_p) * HID;
    else                 src = g_context;
    float4 b = ((const float4*)src)[t];

    int row0 = rg * 16;
    int coff = slice * 256 + t;

    float4 a[16];
#pragma unroll
    for (int r = 0; r < 16; r++)
        a[r] = __ldcs(&((const float4*)(W1 + (size_t)(row0 + r) * UMAT))[coff]);
    float p[16];
#pragma unroll
    for (int r = 0; r < 16; r++) p[r] = dot4(a[r], b);

#pragma unroll
    for (int r = 0; r < 16; r++) {
        float v = warp_sum(p[r]);
        if (lane == 0) sm[r * 8 + wid] = v;
    }
    __syncthreads();
    if (t < 128) {
        float v = sm[t];
#pragma unroll
        for (int o = 4; o > 0; o >>= 1) v += __shfl_xor_sync(0xffffffffu, v, o, 8);
        if ((t & 7) == 0) atomicAdd(&g_hacc[row0 + (t >> 3)], v);
    }
}

// K5: split-K layer-2 partials. 256 blocks = 2 K-slices x 128 groups of 8 rows.
__global__ void k_o(const float* __restrict__ W2, const float* __restrict__ b1) {
    __shared__ float h[HID];
    __shared__ float sm[64];
    int slice = blockIdx.x >> 7;          // 0..1
    int rg    = blockIdx.x & 127;         // 0..127
    int t = threadIdx.x;
    int lane = t & 31, wid = t >> 5;

    {
        float4 aa = ((const float4*)g_hacc)[slice * 256 + t];
        float4 bb = ((const float4*)b1)[slice * 256 + t];
        float4 r;
        float x;
        x = aa.x + bb.x; r.x = 0.5f * x * (1.f + erff(x * 0.70710678118654752f));
        x = aa.y + bb.y; r.y = 0.5f * x * (1.f + erff(x * 0.70710678118654752f));
        x = aa.z + bb.z; r.z = 0.5f * x * (1.f + erff(x * 0.70710678118654752f));
        x = aa.w + bb.w; r.w = 0.5f * x * (1.f + erff(x * 0.70710678118654752f));
        ((float4*)h)[t] = r;
    }
    __syncthreads();

    float4 b = ((const float4*)h)[t];
    int row0 = rg * 8;
    int coff = slice * 256 + t;

    float4 a[8];
#pragma unroll
    for (int r = 0; r < 8; r++)
        a[r] = __ldcs(&((const float4*)(W2 + (size_t)(row0 + r) * DUP))[coff]);
    float p[8];
#pragma unroll
    for (int r = 0; r < 8; r++) p[r] = dot4(a[r], b);

#pragma unroll
    for (int r = 0; r < 8; r++) {
        float v = warp_sum(p[r]);
        if (lane == 0) sm[r * 8 + wid] = v;
    }
    __syncthreads();
    if (t < 64) {
        float v = sm[t];
#pragma unroll
        for (int o = 4; o > 0; o >>= 1) v += __shfl_xor_sync(0xffffffffu, v, o, 8);
        if ((t & 7) == 0) atomicAdd(&g_oacc[row0 + (t >> 3)], v);
    }
}

// K6: LayerNorm over (g_oacc + b2) + residual scatter of row s_i.
__global__ void k_ln_scatter(const float* __restrict__ SE,
                             const float* __restrict__ b2,
                             const float* __restrict__ gamma,
                             const float* __restrict__ beta,
                             const int* __restrict__ s_i_p,
                             float* __restrict__ out) {
    __shared__ float sm[32];
    __shared__ float s_mu, s_rstd;
    int t = threadIdx.x;
    float o = g_oacc[t] + b2[t];

    float v = warp_sum(o);
    if ((t & 31) == 0) sm[t >> 5] = v;
    __syncthreads();
    if (t < 32) {
        v = warp_sum(sm[t]);
        if (t == 0) s_mu = v * (1.f / 1024.f);
    }
    __syncthreads();

    float d = o - s_mu;
    v = warp_sum(d * d);
    __syncthreads();
    if ((t & 31) == 0) sm[t >> 5] = v;
    __syncthreads();
    if (t < 32) {
        v = warp_sum(sm[t]);
        if (t == 0) s_rstd = rsqrtf(v * (1.f / 1024.f) + LN_EPS);
    }
    __syncthreads();

    int si = *s_i_p;
    float hs = SE[(size_t)si * HID + t];
    out[(size_t)si * HID + t] = hs + d * s_rstd * gamma[t] + beta[t];
}

extern "C" void kernel_launch(void* const* d_in, const int* in_sizes, int n_in,
                              void* d_out, int out_size) {
    const float* u_t    = (const float*)d_in[0];
    const float* SE     = (const float*)d_in[1];
    const float* W_attn = (const float*)d_in[2];
    const float* W1     = (const float*)d_in[3];
    const float* b1     = (const float*)d_in[4];
    const float* W2     = (const float*)d_in[5];
    const float* b2     = (const float*)d_in[6];
    const float* gamma  = (const float*)d_in[7];
    const float* beta   = (const float*)d_in[8];
    const int*   s_i    = (const int*)d_in[9];
    float* out = (float*)d_out;

    k_query<<<HID / 8, 256>>>(W_attn, u_t);
    k_fused<<<FUSED_BLOCKS, 256>>>(SE, out);
    k_ctx<<<CTX_BLOCKS, 256>>>();
    k_h<<<3 * 128, 256>>>(W1, u_t, SE, s_i);
    k_o<<<2 * 128, 256>>>(W2, b1);
    k_ln_scatter<<<1, 1024>>>(SE, b2, gamma, beta, s_i, out);
}

// round 8
// speedup vs baseline: 1.9770x; 1.0450x over previous
#include <cuda_runtime.h>
#include <math.h>
#include <stdint.h>

#define N_SPK 65536
#define HID   1024
#define DUP   2048
#define UMAT  3072
#define LN_EPS 1e-5f

#define FUSED_BLOCKS 296                 // 148 SMs x 2 resident blocks
#define WARPS_TOTAL  (FUSED_BLOCKS * 8)  // 2368 persistent warps
#define CTX_BLOCKS   (FUSED_BLOCKS / 8)  // 37 blocks x 8 partials

// ---- scratch (allocation-free: __device__ globals) ----
__device__ float g_query[HID];
__device__ float g_wm[FUSED_BLOCKS];              // per-BLOCK softmax max
__device__ float g_ws[FUSED_BLOCKS];              // per-BLOCK softmax sum
__device__ float g_wv[FUSED_BLOCKS * HID];        // per-BLOCK weighted vectors (1.2 MB)
__device__ float g_context[HID];
__device__ float g_hacc[DUP];                     // split-K partials, layer 1
__device__ float g_oacc[HID];                     // split-K partials, layer 2

__device__ __forceinline__ float warp_sum(float v) {
#pragma unroll
    for (int o = 16; o > 0; o >>= 1) v += __shfl_xor_sync(0xffffffffu, v, o);
    return v;
}
__device__ __forceinline__ float warp_max(float v) {
#pragma unroll
    for (int o = 16; o > 0; o >>= 1) v = fmaxf(v, __shfl_xor_sync(0xffffffffu, v, o));
    return v;
}
__device__ __forceinline__ float dot4(float4 a, float4 b) {
    return a.x * b.x + a.y * b.y + a.z * b.z + a.w * b.w;
}
__device__ __forceinline__ uint32_t smem_u32(const void* p) {
    return (uint32_t)__cvta_generic_to_shared(p);
}
__device__ __forceinline__ void cp_async16(uint32_t dst, const void* src) {
    asm volatile("cp.async.cg.shared.global [%0], [%1], 16;\n" :: "r"(dst), "l"(src));
}
__device__ __forceinline__ void cp_commit_wait_all() {
    asm volatile("cp.async.commit_group;\n");
    asm volatile("cp.async.wait_group 0;\n" ::: "memory");
}

// K1: query = W_attn @ u_t (128 blocks x 8 rows) with cp.async staging.
// Also zeros accumulators.
__global__ void k_query(const float* __restrict__ W_attn, const float* __restrict__ u_t) {
    __shared__ float tile[8 * HID];
    __shared__ float sm[64];
    int gt = blockIdx.x * 256 + threadIdx.x;
    if (gt < HID) g_context[gt] = 0.f;
    if (gt < DUP) g_hacc[gt] = 0.f;
    if (gt < HID) g_oacc[gt] = 0.f;

    int t = threadIdx.x;
    int lane = t & 31, wid = t >> 5;
    int row0 = blockIdx.x * 8;

#pragma unroll
    for (int r = 0; r < 8; r++)
        cp_async16(smem_u32(&tile[r * HID + t * 4]),
                   W_attn + (size_t)(row0 + r) * HID + t * 4);
    float4 b = ((const float4*)u_t)[t];
    cp_commit_wait_all();
    __syncthreads();

    float p[8];
#pragma unroll
    for (int r = 0; r < 8; r++) p[r] = dot4(((const float4*)tile)[r * 256 + t], b);
#pragma unroll
    for (int r = 0; r < 8; r++) {
        float v = warp_sum(p[r]);
        if (lane == 0) sm[r * 8 + wid] = v;
    }
    __syncthreads();
    if (t < 64) {
        float v = sm[t];
#pragma unroll
        for (int o = 4; o > 0; o >>= 1) v += __shfl_xor_sync(0xffffffffu, v, o, 8);
        if ((t & 7) == 0) g_query[row0 + (t >> 3)] = v;
    }
}

// K2: FUSED balanced persistent pass: copy + logits + online-softmax context.
// 296 blocks x 8 warps; warps stride the bank; block merges its 8 warp
// partials in smem and emits ONE (m, s, vec) partial.
__global__ void __launch_bounds__(256, 2)
k_fused(const float* __restrict__ SE, float* __restrict__ out) {
    __shared__ float q[HID];
    __shared__ float s_acc[HID];
    __shared__ float s_m[8], s_s[8];
    for (int i = threadIdx.x; i < HID; i += blockDim.x) q[i] = g_query[i];
    __syncthreads();

    int warp = threadIdx.x >> 5, lane = threadIdx.x & 31;
    int gw = blockIdx.x * 8 + warp;

    const float4* se4  = (const float4*)SE;
    float4*       out4 = (float4*)out;
    const float4* q4   = (const float4*)q;

    float4 v0[8], v1[8], acc[8];
#pragma unroll
    for (int k = 0; k < 8; k++) acc[k] = make_float4(0.f, 0.f, 0.f, 0.f);
    float m = -INFINITY, s = 0.f;

    {
        size_t rb = (size_t)gw * (HID / 4);
#pragma unroll
        for (int k = 0; k < 8; k++) v0[k] = __ldcs(&se4[rb + k * 32 + lane]);
    }

    for (int row = gw; row < N_SPK; row += WARPS_TOTAL) {
        size_t rb = (size_t)row * (HID / 4);
        int nrow = row + WARPS_TOTAL;
        if (nrow < N_SPK) {
            size_t nb = (size_t)nrow * (HID / 4);
#pragma unroll
            for (int k = 0; k < 8; k++) v1[k] = __ldcs(&se4[nb + k * 32 + lane]);
        }
        float p = 0.f;
#pragma unroll
        for (int k = 0; k < 8; k++) p += dot4(v0[k], q4[k * 32 + lane]);
        p = warp_sum(p);

        float mn = fmaxf(m, p);
        float sc = expf(m - mn);        // first iter: exp(-inf)=0
        float wt = expf(p - mn);
        s = s * sc + wt;
        m = mn;
#pragma unroll
        for (int k = 0; k < 8; k++) {
            __stcs(&out4[rb + k * 32 + lane], v0[k]);
            acc[k].x = fmaf(acc[k].x, sc, wt * v0[k].x);
            acc[k].y = fmaf(acc[k].y, sc, wt * v0[k].y);
            acc[k].z = fmaf(acc[k].z, sc, wt * v0[k].z);
            acc[k].w = fmaf(acc[k].w, sc, wt * v0[k].w);
        }
#pragma unroll
        for (int k = 0; k < 8; k++) v0[k] = v1[k];
    }

    // ---- block-level merge of 8 warp partials ----
    if (lane == 0) { s_m[warp] = m; s_s[warp] = s; }
    __syncthreads();
    float Mb = s_m[0];
#pragma unroll
    for (int j = 1; j < 8; j++) Mb = fmaxf(Mb, s_m[j]);
    float Sb = 0.f;
#pragma unroll
    for (int j = 0; j < 8; j++) Sb += s_s[j] * expf(s_m[j] - Mb);
    float scw = expf(m - Mb);

    float4* sa4 = (float4*)s_acc;
    for (int w = 0; w < 8; w++) {
        if (warp == w) {
#pragma unroll
            for (int k = 0; k < 8; k++) {
                int c = k * 32 + lane;
                float4 r;
                if (w == 0) r = make_float4(0.f, 0.f, 0.f, 0.f);
                else        r = sa4[c];
                r.x += acc[k].x * scw;
                r.y += acc[k].y * scw;
                r.z += acc[k].z * scw;
                r.w += acc[k].w * scw;
                sa4[c] = r;
            }
        }
        __syncthreads();
    }

    if (threadIdx.x == 0) { g_wm[blockIdx.x] = Mb; g_ws[blockIdx.x] = Sb; }
    ((float4*)g_wv)[(size_t)blockIdx.x * (HID / 4) + threadIdx.x] = sa4[threadIdx.x];
}

// K3: combine 296 per-block partials -> g_context (37 blocks x 8 partials).
__global__ void k_ctx() {
    __shared__ float sm[32];
    __shared__ float sM, sS;
    __shared__ float e[8];
    int t = threadIdx.x;
    int lane = t & 31, wid = t >> 5;

    float m0 = (t < FUSED_BLOCKS) ? g_wm[t] : -INFINITY;
    float m1 = (t + 256 < FUSED_BLOCKS) ? g_wm[t + 256] : -INFINITY;
    float m = fmaxf(m0, m1);
    m = warp_max(m);
    if (lane == 0) sm[wid] = m;
    __syncthreads();
    if (t < 32) {
        float x = (t < 8) ? sm[t] : -INFINITY;
        x = warp_max(x);
        if (t == 0) sM = x;
    }
    __syncthreads();
    float M = sM;

    float ss = 0.f;
    if (t < FUSED_BLOCKS)       ss += g_ws[t] * expf(m0 - M);
    if (t + 256 < FUSED_BLOCKS) ss += g_ws[t + 256] * expf(m1 - M);
    ss = warp_sum(ss);
    __syncthreads();
    if (lane == 0) sm[wid] = ss;
    __syncthreads();
    if (t < 32) {
        float x = (t < 8) ? sm[t] : 0.f;
        x = warp_sum(x);
        if (t == 0) sS = x;
    }
    __syncthreads();
    float invS = 1.f / sS;

    int wbase = blockIdx.x * 8;
    if (t < 8) e[t] = expf(g_wm[wbase + t] - M) * invS;
    __syncthreads();

    const float4* v4 = (const float4*)g_wv;
    float4 acc = make_float4(0.f, 0.f, 0.f, 0.f);
#pragma unroll
    for (int j = 0; j < 8; j++) {
        float4 v = __ldcs(&v4[(size_t)(wbase + j) * (HID / 4) + t]);
        float ee = e[j];
        acc.x = fmaf(ee, v.x, acc.x);
        acc.y = fmaf(ee, v.y, acc.y);
        acc.z = fmaf(ee, v.z, acc.z);
        acc.w = fmaf(ee, v.w, acc.w);
    }
    float* ctx = g_context + t * 4;
    atomicAdd(ctx + 0, acc.x);
    atomicAdd(ctx + 1, acc.y);
    atomicAdd(ctx + 2, acc.z);
    atomicAdd(ctx + 3, acc.w);
}

// K4: split-K layer-1 partials. 768 blocks = 3 K-slices x 256 groups of 8 rows.
// cp.async stages 8 rows x 4KB into smem (no register landing -> true MLP 8).
__global__ void __launch_bounds__(256)
k_h(const float* __restrict__ W1,
    const float* __restrict__ u_t, const float* __restrict__ SE,
    const int* __restrict__ s_i_p) {
    __shared__ float tile[8 * HID];       // 32 KB
    __shared__ float sm[64];
    int slice = blockIdx.x >> 8;          // 0..2
    int rg    = blockIdx.x & 255;         // 0..255
    int t = threadIdx.x;
    int lane = t & 31, wid = t >> 5;

    int row0 = rg * 8;
    int celt = slice * 1024 + t * 4;      // float offset within W1 row
#pragma unroll
    for (int r = 0; r < 8; r++)
        cp_async16(smem_u32(&tile[r * HID + t * 4]),
                   W1 + (size_t)(row0 + r) * UMAT + celt);

    const float* src;
    if (slice == 0)      src = u_t;
    else if (slice == 1) src = SE + (size_t)(*s_i_p) * HID;
    else                 src = g_context;
    float4 b = ((const float4*)src)[t];

    cp_commit_wait_all();
    __syncthreads();

    float p[8];
#pragma unroll
    for (int r = 0; r < 8; r++) p[r] = dot4(((const float4*)tile)[r * 256 + t], b);
#pragma unroll
    for (int r = 0; r < 8; r++) {
        float v = warp_sum(p[r]);
        if (lane == 0) sm[r * 8 + wid] = v;
    }
    __syncthreads();
    if (t < 64) {
        float v = sm[t];
#pragma unroll
        for (int o = 4; o > 0; o >>= 1) v += __shfl_xor_sync(0xffffffffu, v, o, 8);
        if ((t & 7) == 0) atomicAdd(&g_hacc[row0 + (t >> 3)], v);
    }
}

// K5: split-K layer-2 partials. 256 blocks = 2 K-slices x 128 groups of 8 rows.
// cp.async stages 8 rows x 4KB; gelu(b1+hacc) prologue overlaps the loads.
__global__ void k_o(const float* __restrict__ W2, const float* __restrict__ b1) {
    __shared__ float tile[8 * HID];       // 32 KB
    __shared__ float h[HID];
    __shared__ float sm[64];
    int slice = blockIdx.x >> 7;          // 0..1
    int rg    = blockIdx.x & 127;         // 0..127
    int t = threadIdx.x;
    int lane = t & 31, wid = t >> 5;

    int row0 = rg * 8;
    int celt = slice * 1024 + t * 4;
#pragma unroll
    for (int r = 0; r < 8; r++)
        cp_async16(smem_u32(&tile[r * HID + t * 4]),
                   W2 + (size_t)(row0 + r) * DUP + celt);

    {
        float4 aa = ((const float4*)g_hacc)[slice * 256 + t];
        float4 bb = ((const float4*)b1)[slice * 256 + t];
        float4 r;
        float x;
        x = aa.x + bb.x; r.x = 0.5f * x * (1.f + erff(x * 0.70710678118654752f));
        x = aa.y + bb.y; r.y = 0.5f * x * (1.f + erff(x * 0.70710678118654752f));
        x = aa.z + bb.z; r.z = 0.5f * x * (1.f + erff(x * 0.70710678118654752f));
        x = aa.w + bb.w; r.w = 0.5f * x * (1.f + erff(x * 0.70710678118654752f));
        ((float4*)h)[t] = r;
    }
    cp_commit_wait_all();
    __syncthreads();

    float4 b = ((const float4*)h)[t];
    float p[8];
#pragma unroll
    for (int r = 0; r < 8; r++) p[r] = dot4(((const float4*)tile)[r * 256 + t], b);
#pragma unroll
    for (int r = 0; r < 8; r++) {
        float v = warp_sum(p[r]);
        if (lane == 0) sm[r * 8 + wid] = v;
    }
    __syncthreads();
    if (t < 64) {
        float v = sm[t];
#pragma unroll
        for (int o = 4; o > 0; o >>= 1) v += __shfl_xor_sync(0xffffffffu, v, o, 8);
        if ((t & 7) == 0) atomicAdd(&g_oacc[row0 + (t >> 3)], v);
    }
}

// K6: LayerNorm over (g_oacc + b2) + residual scatter of row s_i.
__global__ void k_ln_scatter(const float* __restrict__ SE,
                             const float* __restrict__ b2,
                             const float* __restrict__ gamma,
                             const float* __restrict__ beta,
                             const int* __restrict__ s_i_p,
                             float* __restrict__ out) {
    __shared__ float sm[32];
    __shared__ float s_mu, s_rstd;
    int t = threadIdx.x;
    float o = g_oacc[t] + b2[t];

    float v = warp_sum(o);
    if ((t & 31) == 0) sm[t >> 5] = v;
    __syncthreads();
    if (t < 32) {
        v = warp_sum(sm[t]);
        if (t == 0) s_mu = v * (1.f / 1024.f);
    }
    __syncthreads();

    float d = o - s_mu;
    v = warp_sum(d * d);
    __syncthreads();
    if ((t & 31) == 0) sm[t >> 5] = v;
    __syncthreads();
    if (t < 32) {
        v = warp_sum(sm[t]);
        if (t == 0) s_rstd = rsqrtf(v * (1.f / 1024.f) + LN_EPS);
    }
    __syncthreads();

    int si = *s_i_p;
    float hs = SE[(size_t)si * HID + t];
    out[(size_t)si * HID + t] = hs + d * s_rstd * gamma[t] + beta[t];
}

extern "C" void kernel_launch(void* const* d_in, const int* in_sizes, int n_in,
                              void* d_out, int out_size) {
    const float* u_t    = (const float*)d_in[0];
    const float* SE     = (const float*)d_in[1];
    const float* W_attn = (const float*)d_in[2];
    const float* W1     = (const float*)d_in[3];
    const float* b1     = (const float*)d_in[4];
    const float* W2     = (const float*)d_in[5];
    const float* b2     = (const float*)d_in[6];
    const float* gamma  = (const float*)d_in[7];
    const float* beta   = (const float*)d_in[8];
    const int*   s_i    = (const int*)d_in[9];
    float* out = (float*)d_out;

    k_query<<<HID / 8, 256>>>(W_attn, u_t);
    k_fused<<<FUSED_BLOCKS, 256>>>(SE, out);
    k_ctx<<<CTX_BLOCKS, 256>>>();
    k_h<<<3 * 256, 256>>>(W1, u_t, SE, s_i);
    k_o<<<2 * 128, 256>>>(W2, b1);
    k_ln_scatter<<<1, 1024>>>(SE, b2, gamma, beta, s_i, out);
}

// round 9
// speedup vs baseline: 2.0031x; 1.0132x over previous
#include <cuda_runtime.h>
#include <math.h>
#include <stdint.h>

#define N_SPK 65536
#define HID   1024
#define DUP   2048
#define UMAT  3072
#define LN_EPS 1e-5f

#define FUSED_BLOCKS 296                 // 148 SMs x 2 resident blocks
#define WARPS_TOTAL  (FUSED_BLOCKS * 8)  // 2368 persistent warps
#define CTX_BLOCKS   (FUSED_BLOCKS / 8)  // 37 blocks x 8 partials

// ---- scratch (allocation-free: __device__ globals) ----
__device__ float g_query[HID];
__device__ float g_wm[FUSED_BLOCKS];              // per-BLOCK softmax max
__device__ float g_ws[FUSED_BLOCKS];              // per-BLOCK softmax sum
__device__ float g_wv[FUSED_BLOCKS * HID];        // per-BLOCK weighted vectors (1.2 MB)
__device__ float g_context[HID];
__device__ float g_hacc[DUP];                     // split-K partials, layer 1
__device__ float g_oacc[HID];                     // split-K partials, layer 2

__device__ __forceinline__ float warp_sum(float v) {
#pragma unroll
    for (int o = 16; o > 0; o >>= 1) v += __shfl_xor_sync(0xffffffffu, v, o);
    return v;
}
__device__ __forceinline__ float warp_max(float v) {
#pragma unroll
    for (int o = 16; o > 0; o >>= 1) v = fmaxf(v, __shfl_xor_sync(0xffffffffu, v, o));
    return v;
}
__device__ __forceinline__ float dot4(float4 a, float4 b) {
    return a.x * b.x + a.y * b.y + a.z * b.z + a.w * b.w;
}
__device__ __forceinline__ uint32_t smem_u32(const void* p) {
    return (uint32_t)__cvta_generic_to_shared(p);
}
__device__ __forceinline__ void cp_async16(uint32_t dst, const void* src) {
    asm volatile("cp.async.cg.shared.global [%0], [%1], 16;\n" :: "r"(dst), "l"(src));
}
__device__ __forceinline__ void cp_commit_wait_all() {
    asm volatile("cp.async.commit_group;\n");
    asm volatile("cp.async.wait_group 0;\n" ::: "memory");
}

// K1: query = W_attn @ u_t (128 blocks x 8 rows) with cp.async staging.
// Also zeros accumulators.
__global__ void k_query(const float* __restrict__ W_attn, const float* __restrict__ u_t) {
    __shared__ float tile[8 * HID];
    __shared__ float sm[64];
    int gt = blockIdx.x * 256 + threadIdx.x;
    if (gt < HID) g_context[gt] = 0.f;
    if (gt < DUP) g_hacc[gt] = 0.f;
    if (gt < HID) g_oacc[gt] = 0.f;

    int t = threadIdx.x;
    int lane = t & 31, wid = t >> 5;
    int row0 = blockIdx.x * 8;

#pragma unroll
    for (int r = 0; r < 8; r++)
        cp_async16(smem_u32(&tile[r * HID + t * 4]),
                   W_attn + (size_t)(row0 + r) * HID + t * 4);
    float4 b = ((const float4*)u_t)[t];
    cp_commit_wait_all();
    __syncthreads();

    float p[8];
#pragma unroll
    for (int r = 0; r < 8; r++) p[r] = dot4(((const float4*)tile)[r * 256 + t], b);
#pragma unroll
    for (int r = 0; r < 8; r++) {
        float v = warp_sum(p[r]);
        if (lane == 0) sm[r * 8 + wid] = v;
    }
    __syncthreads();
    if (t < 64) {
        float v = sm[t];
#pragma unroll
        for (int o = 4; o > 0; o >>= 1) v += __shfl_xor_sync(0xffffffffu, v, o, 8);
        if ((t & 7) == 0) g_query[row0 + (t >> 3)] = v;
    }
}

// K2: FUSED balanced persistent pass: copy + logits + online-softmax context.
__global__ void __launch_bounds__(256, 2)
k_fused(const float* __restrict__ SE, float* __restrict__ out) {
    __shared__ float q[HID];
    __shared__ float s_acc[HID];
    __shared__ float s_m[8], s_s[8];
    for (int i = threadIdx.x; i < HID; i += blockDim.x) q[i] = g_query[i];
    __syncthreads();

    int warp = threadIdx.x >> 5, lane = threadIdx.x & 31;
    int gw = blockIdx.x * 8 + warp;

    const float4* se4  = (const float4*)SE;
    float4*       out4 = (float4*)out;
    const float4* q4   = (const float4*)q;

    float4 v0[8], v1[8], acc[8];
#pragma unroll
    for (int k = 0; k < 8; k++) acc[k] = make_float4(0.f, 0.f, 0.f, 0.f);
    float m = -INFINITY, s = 0.f;

    {
        size_t rb = (size_t)gw * (HID / 4);
#pragma unroll
        for (int k = 0; k < 8; k++) v0[k] = __ldcs(&se4[rb + k * 32 + lane]);
    }

    for (int row = gw; row < N_SPK; row += WARPS_TOTAL) {
        size_t rb = (size_t)row * (HID / 4);
        int nrow = row + WARPS_TOTAL;
        if (nrow < N_SPK) {
            size_t nb = (size_t)nrow * (HID / 4);
#pragma unroll
            for (int k = 0; k < 8; k++) v1[k] = __ldcs(&se4[nb + k * 32 + lane]);
        }
        float p = 0.f;
#pragma unroll
        for (int k = 0; k < 8; k++) p += dot4(v0[k], q4[k * 32 + lane]);
        p = warp_sum(p);

        float mn = fmaxf(m, p);
        float sc = expf(m - mn);        // first iter: exp(-inf)=0
        float wt = expf(p - mn);
        s = s * sc + wt;
        m = mn;
#pragma unroll
        for (int k = 0; k < 8; k++) {
            __stcs(&out4[rb + k * 32 + lane], v0[k]);
            acc[k].x = fmaf(acc[k].x, sc, wt * v0[k].x);
            acc[k].y = fmaf(acc[k].y, sc, wt * v0[k].y);
            acc[k].z = fmaf(acc[k].z, sc, wt * v0[k].z);
            acc[k].w = fmaf(acc[k].w, sc, wt * v0[k].w);
        }
#pragma unroll
        for (int k = 0; k < 8; k++) v0[k] = v1[k];
    }

    // ---- block-level merge of 8 warp partials ----
    if (lane == 0) { s_m[warp] = m; s_s[warp] = s; }
    __syncthreads();
    float Mb = s_m[0];
#pragma unroll
    for (int j = 1; j < 8; j++) Mb = fmaxf(Mb, s_m[j]);
    float Sb = 0.f;
#pragma unroll
    for (int j = 0; j < 8; j++) Sb += s_s[j] * expf(s_m[j] - Mb);
    float scw = expf(m - Mb);

    float4* sa4 = (float4*)s_acc;
    for (int w = 0; w < 8; w++) {
        if (warp == w) {
#pragma unroll
            for (int k = 0; k < 8; k++) {
                int c = k * 32 + lane;
                float4 r;
                if (w == 0) r = make_float4(0.f, 0.f, 0.f, 0.f);
                else        r = sa4[c];
                r.x += acc[k].x * scw;
                r.y += acc[k].y * scw;
                r.z += acc[k].z * scw;
                r.w += acc[k].w * scw;
                sa4[c] = r;
            }
        }
        __syncthreads();
    }

    if (threadIdx.x == 0) { g_wm[blockIdx.x] = Mb; g_ws[blockIdx.x] = Sb; }
    ((float4*)g_wv)[(size_t)blockIdx.x * (HID / 4) + threadIdx.x] = sa4[threadIdx.x];
}

// K3: combine 296 per-block partials -> g_context (37 blocks x 8 partials).
__global__ void k_ctx() {
    __shared__ float sm[32];
    __shared__ float sM, sS;
    __shared__ float e[8];
    int t = threadIdx.x;
    int lane = t & 31, wid = t >> 5;

    float m0 = (t < FUSED_BLOCKS) ? g_wm[t] : -INFINITY;
    float m1 = (t + 256 < FUSED_BLOCKS) ? g_wm[t + 256] : -INFINITY;
    float m = fmaxf(m0, m1);
    m = warp_max(m);
    if (lane == 0) sm[wid] = m;
    __syncthreads();
    if (t < 32) {
        float x = (t < 8) ? sm[t] : -INFINITY;
        x = warp_max(x);
        if (t == 0) sM = x;
    }
    __syncthreads();
    float M = sM;

    float ss = 0.f;
    if (t < FUSED_BLOCKS)       ss += g_ws[t] * expf(m0 - M);
    if (t + 256 < FUSED_BLOCKS) ss += g_ws[t + 256] * expf(m1 - M);
    ss = warp_sum(ss);
    __syncthreads();
    if (lane == 0) sm[wid] = ss;
    __syncthreads();
    if (t < 32) {
        float x = (t < 8) ? sm[t] : 0.f;
        x = warp_sum(x);
        if (t == 0) sS = x;
    }
    __syncthreads();
    float invS = 1.f / sS;

    int wbase = blockIdx.x * 8;
    if (t < 8) e[t] = expf(g_wm[wbase + t] - M) * invS;
    __syncthreads();

    const float4* v4 = (const float4*)g_wv;
    float4 acc = make_float4(0.f, 0.f, 0.f, 0.f);
#pragma unroll
    for (int j = 0; j < 8; j++) {
        float4 v = __ldcs(&v4[(size_t)(wbase + j) * (HID / 4) + t]);
        float ee = e[j];
        acc.x = fmaf(ee, v.x, acc.x);
        acc.y = fmaf(ee, v.y, acc.y);
        acc.z = fmaf(ee, v.z, acc.z);
        acc.w = fmaf(ee, v.w, acc.w);
    }
    float* ctx = g_context + t * 4;
    atomicAdd(ctx + 0, acc.x);
    atomicAdd(ctx + 1, acc.y);
    atomicAdd(ctx + 2, acc.z);
    atomicAdd(ctx + 3, acc.w);
}

// K4a: layer-1 partials for K-slices 0 and 1 (u_t, SE[s_i]) — NO context
// dependency, so this runs CONCURRENTLY with k_fused on a side stream.
// 512 blocks = 2 slices x 256 groups of 8 rows; cp.async staging.
__global__ void __launch_bounds__(256)
k_h01(const float* __restrict__ W1,
      const float* __restrict__ u_t, const float* __restrict__ SE,
      const int* __restrict__ s_i_p) {
    __shared__ float tile[8 * HID];       // 32 KB
    __shared__ float sm[64];
    int slice = blockIdx.x >> 8;          // 0..1
    int rg    = blockIdx.x & 255;         // 0..255
    int t = threadIdx.x;
    int lane = t & 31, wid = t >> 5;

    int row0 = rg * 8;
    int celt = slice * 1024 + t * 4;
#pragma unroll
    for (int r = 0; r < 8; r++)
        cp_async16(smem_u32(&tile[r * HID + t * 4]),
                   W1 + (size_t)(row0 + r) * UMAT + celt);

    const float* src = (slice == 0) ? u_t : (SE + (size_t)(*s_i_p) * HID);
    float4 b = ((const float4*)src)[t];

    cp_commit_wait_all();
    __syncthreads();

    float p[8];
#pragma unroll
    for (int r = 0; r < 8; r++) p[r] = dot4(((const float4*)tile)[r * 256 + t], b);
#pragma unroll
    for (int r = 0; r < 8; r++) {
        float v = warp_sum(p[r]);
        if (lane == 0) sm[r * 8 + wid] = v;
    }
    __syncthreads();
    if (t < 64) {
        float v = sm[t];
#pragma unroll
        for (int o = 4; o > 0; o >>= 1) v += __shfl_xor_sync(0xffffffffu, v, o, 8);
        if ((t & 7) == 0) atomicAdd(&g_hacc[row0 + (t >> 3)], v);
    }
}

// K4b: layer-1 partials for K-slice 2 (context). Runs after k_ctx.
// 256 blocks x 8 rows.
__global__ void __launch_bounds__(256)
k_h2(const float* __restrict__ W1) {
    __shared__ float tile[8 * HID];       // 32 KB
    __shared__ float sm[64];
    int rg = blockIdx.x;                  // 0..255
    int t = threadIdx.x;
    int lane = t & 31, wid = t >> 5;

    int row0 = rg * 8;
    int celt = 2048 + t * 4;
#pragma unroll
    for (int r = 0; r < 8; r++)
        cp_async16(smem_u32(&tile[r * HID + t * 4]),
                   W1 + (size_t)(row0 + r) * UMAT + celt);

    float4 b = ((const float4*)g_context)[t];
    cp_commit_wait_all();
    __syncthreads();

    float p[8];
#pragma unroll
    for (int r = 0; r < 8; r++) p[r] = dot4(((const float4*)tile)[r * 256 + t], b);
#pragma unroll
    for (int r = 0; r < 8; r++) {
        float v = warp_sum(p[r]);
        if (lane == 0) sm[r * 8 + wid] = v;
    }
    __syncthreads();
    if (t < 64) {
        float v = sm[t];
#pragma unroll
        for (int o = 4; o > 0; o >>= 1) v += __shfl_xor_sync(0xffffffffu, v, o, 8);
        if ((t & 7) == 0) atomicAdd(&g_hacc[row0 + (t >> 3)], v);
    }
}

// K5: split-K layer-2 partials. 256 blocks = 2 K-slices x 128 groups of 8 rows.
__global__ void k_o(const float* __restrict__ W2, const float* __restrict__ b1) {
    __shared__ float tile[8 * HID];       // 32 KB
    __shared__ float h[HID];
    __shared__ float sm[64];
    int slice = blockIdx.x >> 7;          // 0..1
    int rg    = blockIdx.x & 127;         // 0..127
    int t = threadIdx.x;
    int lane = t & 31, wid = t >> 5;

    int row0 = rg * 8;
    int celt = slice * 1024 + t * 4;
#pragma unroll
    for (int r = 0; r < 8; r++)
        cp_async16(smem_u32(&tile[r * HID + t * 4]),
                   W2 + (size_t)(row0 + r) * DUP + celt);

    {
        float4 aa = ((const float4*)g_hacc)[slice * 256 + t];
        float4 bb = ((const float4*)b1)[slice * 256 + t];
        float4 r;
        float x;
        x = aa.x + bb.x; r.x = 0.5f * x * (1.f + erff(x * 0.70710678118654752f));
        x = aa.y + bb.y; r.y = 0.5f * x * (1.f + erff(x * 0.70710678118654752f));
        x = aa.z + bb.z; r.z = 0.5f * x * (1.f + erff(x * 0.70710678118654752f));
        x = aa.w + bb.w; r.w = 0.5f * x * (1.f + erff(x * 0.70710678118654752f));
        ((float4*)h)[t] = r;
    }
    cp_commit_wait_all();
    __syncthreads();

    float4 b = ((const float4*)h)[t];
    float p[8];
#pragma unroll
    for (int r = 0; r < 8; r++) p[r] = dot4(((const float4*)tile)[r * 256 + t], b);
#pragma unroll
    for (int r = 0; r < 8; r++) {
        float v = warp_sum(p[r]);
        if (lane == 0) sm[r * 8 + wid] = v;
    }
    __syncthreads();
    if (t < 64) {
        float v = sm[t];
#pragma unroll
        for (int o = 4; o > 0; o >>= 1) v += __shfl_xor_sync(0xffffffffu, v, o, 8);
        if ((t & 7) == 0) atomicAdd(&g_oacc[row0 + (t >> 3)], v);
    }
}

// K6: LayerNorm over (g_oacc + b2) + residual scatter of row s_i.
__global__ void k_ln_scatter(const float* __restrict__ SE,
                             const float* __restrict__ b2,
                             const float* __restrict__ gamma,
                             const float* __restrict__ beta,
                             const int* __restrict__ s_i_p,
                             float* __restrict__ out) {
    __shared__ float sm[32];
    __shared__ float s_mu, s_rstd;
    int t = threadIdx.x;
    float o = g_oacc[t] + b2[t];

    float v = warp_sum(o);
    if ((t & 31) == 0) sm[t >> 5] = v;
    __syncthreads();
    if (t < 32) {
        v = warp_sum(sm[t]);
        if (t == 0) s_mu = v * (1.f / 1024.f);
    }
    __syncthreads();

    float d = o - s_mu;
    v = warp_sum(d * d);
    __syncthreads();
    if ((t & 31) == 0) sm[t >> 5] = v;
    __syncthreads();
    if (t < 32) {
        v = warp_sum(sm[t]);
        if (t == 0) s_rstd = rsqrtf(v * (1.f / 1024.f) + LN_EPS);
    }
    __syncthreads();

    int si = *s_i_p;
    float hs = SE[(size_t)si * HID + t];
    out[(size_t)si * HID + t] = hs + d * s_rstd * gamma[t] + beta[t];
}

extern "C" void kernel_launch(void* const* d_in, const int* in_sizes, int n_in,
                              void* d_out, int out_size) {
    const float* u_t    = (const float*)d_in[0];
    const float* SE     = (const float*)d_in[1];
    const float* W_attn = (const float*)d_in[2];
    const float* W1     = (const float*)d_in[3];
    const float* b1     = (const float*)d_in[4];
    const float* W2     = (const float*)d_in[5];
    const float* b2     = (const float*)d_in[6];
    const float* gamma  = (const float*)d_in[7];
    const float* beta   = (const float*)d_in[8];
    const int*   s_i    = (const int*)d_in[9];
    float* out = (float*)d_out;

    // Lazy one-time stream/event creation (happens on the first, non-captured
    // correctness call; reused identically on every later call).
    static cudaStream_t s_side = nullptr;
    static cudaEvent_t  ev_q = nullptr, ev_h = nullptr;
    if (s_side == nullptr) {
        cudaStreamCreateWithFlags(&s_side, cudaStreamNonBlocking);
        cudaEventCreateWithFlags(&ev_q, cudaEventDisableTiming);
        cudaEventCreateWithFlags(&ev_h, cudaEventDisableTiming);
    }

    // main stream (legacy default)
    k_query<<<HID / 8, 256>>>(W_attn, u_t);
    cudaEventRecord(ev_q, 0);

    // side stream: W1 slices 0/1 overlap with the big fused pass
    cudaStreamWaitEvent(s_side, ev_q, 0);
    k_h01<<<2 * 256, 256, 0, s_side>>>(W1, u_t, SE, s_i);
    cudaEventRecord(ev_h, s_side);

    // main stream: fused bank pass -> softmax combine -> context slice
    k_fused<<<FUSED_BLOCKS, 256>>>(SE, out);
    k_ctx<<<CTX_BLOCKS, 256>>>();
    k_h2<<<256, 256>>>(W1);

    // join side stream, then layer 2 + LN
    cudaStreamWaitEvent(0, ev_h, 0);
    k_o<<<2 * 128, 256>>>(W2, b1);
    k_ln_scatter<<<1, 1024>>>(SE, b2, gamma, beta, s_i, out);
}